// round 9
// baseline (speedup 1.0000x reference)
#include <cuda_runtime.h>
#include <math.h>
#include <stdint.h>

#define LL 2
#define BB 2
#define SS 1024
#define DD 1024
#define HH 16
#define HDD 64
#define FFD 4096
#define VV 32000
#define RR 16
#define MM (BB*SS)
#define LORA_SCALE 2.0f
#define EPSV 1e-6f

__device__ float g_x2  [2L*MM*DD];
__device__ float g_h2  [2L*MM*DD];
__device__ float g_qkv2[2L*MM*3*DD];
__device__ float g_o2  [2L*MM*DD];
__device__ float g_u2  [2L*MM*FFD];
__device__ float g_t   [MM*RR];
__device__ float g_wcat[DD*3*DD];
__device__ float g_woc [DD*DD];
__device__ float g_w1c [DD*FFD];
__device__ float g_w2c [FFD*DD];
__device__ float g_lmc [DD*VV];

__device__ __forceinline__ float blk_sum(float v, float* sm) {
    int tid = threadIdx.x;
    sm[tid] = v; __syncthreads();
    for (int s = 128; s > 0; s >>= 1) { if (tid < s) sm[tid] += sm[tid + s]; __syncthreads(); }
    float r = sm[0]; __syncthreads(); return r;
}
__device__ __forceinline__ float cvtf(float x) {
    uint32_t u; asm("cvt.rna.tf32.f32 %0, %1;" : "=r"(u) : "f"(x));
    return __uint_as_float(u);
}
__device__ __forceinline__ void cpa16(float* dst, const float* src) {
    uint32_t d = (uint32_t)__cvta_generic_to_shared(dst);
    asm volatile("cp.async.cg.shared.global [%0], [%1], 16;" :: "r"(d), "l"(src));
}
__device__ __forceinline__ void cpa_commit() { asm volatile("cp.async.commit_group;" ::: "memory"); }
__device__ __forceinline__ void cpa_wait0()  { asm volatile("cp.async.wait_group 0;" ::: "memory"); }
__device__ __forceinline__ float fast_tanh(float x) {
    float e = __expf(2.f * x);
    return 1.f - 2.f / (e + 1.f);
}
__device__ __forceinline__ void mma8(float* c, const uint32_t* a, const uint32_t* b) {
    asm volatile(
        "mma.sync.aligned.m16n8k8.row.col.f32.tf32.tf32.f32 "
        "{%0,%1,%2,%3}, {%4,%5,%6,%7}, {%8,%9}, {%0,%1,%2,%3};"
        : "+f"(c[0]), "+f"(c[1]), "+f"(c[2]), "+f"(c[3])
        : "r"(a[0]), "r"(a[1]), "r"(a[2]), "r"(a[3]), "r"(b[0]), "r"(b[1]));
}

__global__ void embed_kernel(const int* __restrict__ ids, const float* __restrict__ emb,
                             float* __restrict__ x, float* __restrict__ dx) {
    long i = (long)blockIdx.x * blockDim.x + threadIdx.x;
    int col = (int)(i % DD), row = (int)(i / DD);
    x[i]  = emb[(long)ids[row] * DD + col];
    dx[i] = 0.f;
}

__global__ void cvtcopy_kernel(const float* __restrict__ in, float* __restrict__ out) {
    long i = (long)blockIdx.x * blockDim.x + threadIdx.x;
    float4 v = ((const float4*)in)[i];
    ((float4*)out)[i] = make_float4(cvtf(v.x), cvtf(v.y), cvtf(v.z), cvtf(v.w));
}

__global__ void catw_kernel(const float* __restrict__ Wq, const float* __restrict__ Wk,
                            const float* __restrict__ Wv, float* __restrict__ out) {
    long i = (long)blockIdx.x * blockDim.x + threadIdx.x;
    int d = (int)(i / DD), j = (int)(i % DD);
    out[(long)d * 3*DD + j]        = cvtf(Wq[i]);
    out[(long)d * 3*DD + DD + j]   = cvtf(Wk[i]);
    out[(long)d * 3*DD + 2*DD + j] = cvtf(Wv[i]);
}

__global__ void rms_jvp_kernel(const float* __restrict__ x, const float* __restrict__ dx,
                               const float* __restrict__ g,
                               float* __restrict__ h, float* __restrict__ dh) {
    __shared__ float sm[256];
    int row = blockIdx.x, tid = threadIdx.x;
    const float* xr  = x  + (long)row * DD;
    const float* dxr = dx + (long)row * DD;
    float* hr  = h  + (long)row * DD;
    float* dhr = dh + (long)row * DD;
    float s2 = 0.f, sxd = 0.f;
    for (int i = tid; i < DD; i += 256) { float xv = xr[i], dv = dxr[i]; s2 += xv*xv; sxd += xv*dv; }
    s2  = blk_sum(s2,  sm);
    sxd = blk_sum(sxd, sm);
    float r = rsqrtf(s2 / (float)DD + EPSV);
    float c = (sxd / (float)DD) * r * r * r;
    for (int i = tid; i < DD; i += 256) {
        float xv = xr[i], dv = dxr[i], gv = g[i];
        hr[i]  = cvtf(xv * gv * r);
        dhr[i] = cvtf(gv * (dv * r - xv * c));
    }
}

__global__ void rms_final_kernel(const float* __restrict__ x, const float* __restrict__ dx,
                                 const float* __restrict__ g, float* __restrict__ out) {
    __shared__ float sm[256];
    int row = blockIdx.x, tid = threadIdx.x;
    const float* xr  = x  + (long)row * DD;
    const float* dxr = dx + (long)row * DD;
    float* orow = out + (long)row * DD;
    float s2 = 0.f, sxd = 0.f;
    for (int i = tid; i < DD; i += 256) { float xv = xr[i], dv = dxr[i]; s2 += xv*xv; sxd += xv*dv; }
    s2  = blk_sum(s2,  sm);
    sxd = blk_sum(sxd, sm);
    float r = rsqrtf(s2 / (float)DD + EPSV);
    float c = (sxd / (float)DD) * r * r * r;
    for (int i = tid; i < DD; i += 256) {
        float xv = xr[i], dv = dxr[i], gv = g[i];
        orow[i] = cvtf(xv * gv * r + gv * (dv * r - xv * c));
    }
}

__global__ void gelu_jvp_kernel(float* __restrict__ u, float* __restrict__ du) {
    long i = (long)blockIdx.x * blockDim.x + threadIdx.x;
    float x = u[i], d = du[i];
    const float c0 = 0.7978845608028654f, c1 = 0.044715f;
    float x2 = x * x;
    float t  = fast_tanh(c0 * (x + c1 * x * x2));
    float gl = 0.5f * x * (1.f + t);
    float dg = 0.5f * (1.f + t) + 0.5f * x * (1.f - t*t) * c0 * (1.f + 3.f * c1 * x2);
    u[i]  = cvtf(gl);
    du[i] = cvtf(dg * d);
}

// ===== fused attention JVP (unchanged from R8) =====
#define AT_LD 68
#define AT_LDV 72
#define AT_T68 (64*AT_LD)
#define AT_T72 (64*AT_LDV)
#define SQ    0
#define SDQ   (SQ + AT_T68)
#define SK    (SDQ + AT_T68)
#define SDK   (SK + 2*AT_T68)
#define SV    (SDK + 2*AT_T68)
#define SDV   (SV + 2*AT_T72)
#define SP    (SDV + 2*AT_T72)
#define SPDS  (SP + AT_T68)
#define SLRED (SPDS + AT_T68)
#define STRED (SLRED + 256)
#define SLRUN (STRED + 256)
#define STRUN (SLRUN + 64)
#define AT_FLOATS (STRUN + 64)

__global__ __launch_bounds__(256)
void attn_jvp_kernel(const float* __restrict__ qkv, float* __restrict__ o2p,
                     float* __restrict__ o2t, int has_dk)
{
    extern __shared__ float smem[];
    int mb = 15 - blockIdx.x;
    int bh = blockIdx.y;
    int b = bh >> 4, hh = bh & 15;
    int m0 = mb * 64;
    int nc = mb + 1;
    const long RW = 3 * DD;
    const long PRJ = (long)MM * 3 * DD;
    const float* qp = qkv + (long)(b*SS + m0) * RW + hh * HDD;
    int tid = threadIdx.x;
    int lane = tid & 31, wid = tid >> 5;
    int wm = wid >> 2, wn = wid & 3;
    int r = lane >> 2, cq = lane & 3;

    if (tid < 64) { smem[SLRUN + tid] = 0.f; smem[STRUN + tid] = 0.f; }

    {
        const float* kp = qkv + (long)(b*SS) * RW + DD + hh * HDD;
        const float* vp = qkv + (long)(b*SS) * RW + 2*DD + hh * HDD;
        #pragma unroll
        for (int i = 0; i < 4; i++) {
            int idx = tid + i * 256; int row = idx >> 4; int c4 = idx & 15;
            cpa16(&smem[SQ  + row*AT_LD  + c4*4], qp + (long)row * RW + c4*4);
            cpa16(&smem[SDQ + row*AT_LD  + c4*4], qp + PRJ + (long)row * RW + c4*4);
            cpa16(&smem[SK  + row*AT_LD  + c4*4], kp + (long)row * RW + c4*4);
            cpa16(&smem[SV  + row*AT_LDV + c4*4], vp + (long)row * RW + c4*4);
            cpa16(&smem[SDV + row*AT_LDV + c4*4], vp + PRJ + (long)row * RW + c4*4);
            if (has_dk)
                cpa16(&smem[SDK + row*AT_LD + c4*4], kp + PRJ + (long)row * RW + c4*4);
        }
        cpa_commit();
    }

    float o1[2][2][4] = {}, o2a[2][2][4] = {}, o3[2][2][4] = {};

    for (int ic = 0; ic < nc; ic++) {
        cpa_wait0();
        __syncthreads();
        int cur = ic & 1;
        if (ic + 1 < nc) {
            int nxt = (ic + 1) & 1;
            int kb = (ic + 1) * 64;
            const float* kp = qkv + (long)(b*SS + kb) * RW + DD + hh * HDD;
            const float* vp = qkv + (long)(b*SS + kb) * RW + 2*DD + hh * HDD;
            #pragma unroll
            for (int i = 0; i < 4; i++) {
                int idx = tid + i * 256; int row = idx >> 4; int c4 = idx & 15;
                cpa16(&smem[SK  + nxt*AT_T68 + row*AT_LD  + c4*4], kp + (long)row * RW + c4*4);
                cpa16(&smem[SV  + nxt*AT_T72 + row*AT_LDV + c4*4], vp + (long)row * RW + c4*4);
                cpa16(&smem[SDV + nxt*AT_T72 + row*AT_LDV + c4*4], vp + PRJ + (long)row * RW + c4*4);
                if (has_dk)
                    cpa16(&smem[SDK + nxt*AT_T68 + row*AT_LD + c4*4], kp + PRJ + (long)row * RW + c4*4);
            }
            cpa_commit();
        }
        const float* Ks  = smem + SK  + cur * AT_T68;
        const float* dKs = smem + SDK + cur * AT_T68;
        const float* Vs  = smem + SV  + cur * AT_T72;
        const float* dVs = smem + SDV + cur * AT_T72;

        float sacc[2][2][4] = {}, dsacc[2][2][4] = {};
        #pragma unroll
        for (int ks = 0; ks < 64; ks += 8) {
            uint32_t aq[2][4], adq[2][4], bk[2][2], bdk[2][2];
            #pragma unroll
            for (int mt = 0; mt < 2; mt++) {
                int base = (wm*32 + mt*16 + r) * AT_LD + ks + cq;
                aq[mt][0]  = __float_as_uint(smem[SQ  + base]);
                aq[mt][1]  = __float_as_uint(smem[SQ  + base + 8*AT_LD]);
                aq[mt][2]  = __float_as_uint(smem[SQ  + base + 4]);
                aq[mt][3]  = __float_as_uint(smem[SQ  + base + 8*AT_LD + 4]);
                adq[mt][0] = __float_as_uint(smem[SDQ + base]);
                adq[mt][1] = __float_as_uint(smem[SDQ + base + 8*AT_LD]);
                adq[mt][2] = __float_as_uint(smem[SDQ + base + 4]);
                adq[mt][3] = __float_as_uint(smem[SDQ + base + 8*AT_LD + 4]);
            }
            #pragma unroll
            for (int nt = 0; nt < 2; nt++) {
                int boff = (wn*16 + nt*8 + r) * AT_LD + ks + cq;
                bk[nt][0] = __float_as_uint(Ks[boff]);
                bk[nt][1] = __float_as_uint(Ks[boff + 4]);
                if (has_dk) {
                    bdk[nt][0] = __float_as_uint(dKs[boff]);
                    bdk[nt][1] = __float_as_uint(dKs[boff + 4]);
                }
            }
            #pragma unroll
            for (int mt = 0; mt < 2; mt++)
                #pragma unroll
                for (int nt = 0; nt < 2; nt++) {
                    mma8(sacc[mt][nt], aq[mt], bk[nt]);
                    mma8(dsacc[mt][nt], adq[mt], bk[nt]);
                    if (has_dk) mma8(dsacc[mt][nt], aq[mt], bdk[nt]);
                }
        }

        int diag = (ic == mb);
        float lp[2][2] = {}, tp[2][2] = {};
        #pragma unroll
        for (int mt = 0; mt < 2; mt++)
            #pragma unroll
            for (int nt = 0; nt < 2; nt++)
                #pragma unroll
                for (int j = 0; j < 4; j++) {
                    int row = wm*32 + mt*16 + r + (j >> 1) * 8;
                    int col = wn*16 + nt*8 + cq*2 + (j & 1);
                    float s  = sacc[mt][nt][j]  * 0.125f;
                    float ds = dsacc[mt][nt][j] * 0.125f;
                    float pv = (diag && col > row) ? 0.f : cvtf(__expf(s));
                    float pd = cvtf(pv * ds);
                    smem[SP   + row*AT_LD + col] = pv;
                    smem[SPDS + row*AT_LD + col] = pd;
                    lp[mt][j>>1] += pv;
                    tp[mt][j>>1] += pd;
                }
        #pragma unroll
        for (int mt = 0; mt < 2; mt++)
            #pragma unroll
            for (int hf = 0; hf < 2; hf++) {
                float lv = lp[mt][hf], tv = tp[mt][hf];
                lv += __shfl_xor_sync(0xffffffff, lv, 1);
                lv += __shfl_xor_sync(0xffffffff, lv, 2);
                tv += __shfl_xor_sync(0xffffffff, tv, 1);
                tv += __shfl_xor_sync(0xffffffff, tv, 2);
                if (cq == 0) {
                    int row = wm*32 + mt*16 + r + hf*8;
                    smem[SLRED + row*4 + wn] = lv;
                    smem[STRED + row*4 + wn] = tv;
                }
            }
        __syncthreads();
        if (tid < 64) {
            smem[SLRUN + tid] += smem[SLRED + tid*4] + smem[SLRED + tid*4+1]
                               + smem[SLRED + tid*4+2] + smem[SLRED + tid*4+3];
            smem[STRUN + tid] += smem[STRED + tid*4] + smem[STRED + tid*4+1]
                               + smem[STRED + tid*4+2] + smem[STRED + tid*4+3];
        }

        #pragma unroll
        for (int ks = 0; ks < 64; ks += 8) {
            uint32_t ap[2][4], apd[2][4], bv[2][2], bdv[2][2];
            #pragma unroll
            for (int mt = 0; mt < 2; mt++) {
                int base = (wm*32 + mt*16 + r) * AT_LD + ks + cq;
                ap[mt][0]  = __float_as_uint(smem[SP   + base]);
                ap[mt][1]  = __float_as_uint(smem[SP   + base + 8*AT_LD]);
                ap[mt][2]  = __float_as_uint(smem[SP   + base + 4]);
                ap[mt][3]  = __float_as_uint(smem[SP   + base + 8*AT_LD + 4]);
                apd[mt][0] = __float_as_uint(smem[SPDS + base]);
                apd[mt][1] = __float_as_uint(smem[SPDS + base + 8*AT_LD]);
                apd[mt][2] = __float_as_uint(smem[SPDS + base + 4]);
                apd[mt][3] = __float_as_uint(smem[SPDS + base + 8*AT_LD + 4]);
            }
            #pragma unroll
            for (int nt = 0; nt < 2; nt++) {
                int nb = wn*16 + nt*8;
                bv[nt][0]  = __float_as_uint(Vs[(ks + cq) * AT_LDV + nb + r]);
                bv[nt][1]  = __float_as_uint(Vs[(ks + cq + 4) * AT_LDV + nb + r]);
                bdv[nt][0] = __float_as_uint(dVs[(ks + cq) * AT_LDV + nb + r]);
                bdv[nt][1] = __float_as_uint(dVs[(ks + cq + 4) * AT_LDV + nb + r]);
            }
            #pragma unroll
            for (int mt = 0; mt < 2; mt++)
                #pragma unroll
                for (int nt = 0; nt < 2; nt++) {
                    mma8(o1[mt][nt],  ap[mt],  bv[nt]);
                    mma8(o2a[mt][nt], apd[mt], bv[nt]);
                    mma8(o3[mt][nt],  ap[mt],  bdv[nt]);
                }
        }
    }

    __syncthreads();
    #pragma unroll
    for (int mt = 0; mt < 2; mt++)
        #pragma unroll
        for (int nt = 0; nt < 2; nt++)
            #pragma unroll
            for (int hf = 0; hf < 2; hf++) {
                int lrow = wm*32 + mt*16 + r + hf*8;
                float inv = 1.f / smem[SLRUN + lrow];
                float tf = smem[STRUN + lrow] * inv;
                int j0 = hf * 2;
                float oa = o1[mt][nt][j0]   * inv;
                float ob = o1[mt][nt][j0+1] * inv;
                float da = (o2a[mt][nt][j0]   - tf * o1[mt][nt][j0])   * inv + o3[mt][nt][j0]   * inv;
                float db = (o2a[mt][nt][j0+1] - tf * o1[mt][nt][j0+1]) * inv + o3[mt][nt][j0+1] * inv;
                long idx = (long)(b*SS + m0 + lrow) * DD + hh * HDD + wn*16 + nt*8 + cq*2;
                *(float2*)(o2p + idx) = make_float2(cvtf(oa), cvtf(ob));
                *(float2*)(o2t + idx) = make_float2(cvtf(da), cvtf(db));
            }
}

// ===== TF32 GEMM: 64x64 warp tiles; BN=128 (128 thr, 2 CTA/SM) or BN=256 (256 thr) =====
template<int BN_, bool CVTO>
__global__ __launch_bounds__(BN_, BN_ == 128 ? 2 : 1)
void tc_gemm_kernel(const float* __restrict__ A, const float* __restrict__ B,
                    float* __restrict__ C, int M, int N, int K,
                    int lda, int ldb, int ldc, float alpha, float beta)
{
    extern __shared__ float smem[];
    constexpr int NT = BN_;                  // threads
    constexpr int LDA_S = 36;
    constexpr int LDB_S = BN_ + 8;
    constexpr int ASZ = 128 * LDA_S;
    constexpr int BSZ = 32 * LDB_S;
    constexpr int STG = ASZ + BSZ;
    constexpr int NWN = BN_ / 64;            // warp cols

    int m0 = blockIdx.y * 128, n0 = blockIdx.x * BN_;
    int nIt = K >> 5;
    int tid = threadIdx.x;
    int lane = tid & 31, wid = tid >> 5;
    int wm = wid & 1, wn = wid >> 1;         // 2 x NWN warp grid
    int r = lane >> 2, cq = lane & 3;

    auto LOAD = [&](int kt, int st) {
        float* As = smem + st * STG;
        float* Bs = As + ASZ;
        int k0 = kt * 32;
        {   // A: 128 x 32 = 1024 float4
            int kk4 = tid & 7, mr = tid >> 3;
            constexpr int MP = NT / 8;       // rows per pass
            #pragma unroll
            for (int i = 0; i < 128 / MP; i++) {
                int m = mr + i * MP;
                cpa16(&As[m * LDA_S + kk4 * 4], A + (long)(m0 + m) * lda + k0 + kk4 * 4);
            }
        }
        {   // B: 32 x BN_ ; BN_/4 float4 per k-row
            constexpr int NP4 = BN_ / 4;
            int n4 = tid % NP4, kr = tid / NP4;   // kr in 0..3
            #pragma unroll
            for (int i = 0; i < 8; i++) {
                int kk = kr + i * 4;
                cpa16(&Bs[kk * LDB_S + n4 * 4], B + (long)(k0 + kk) * ldb + n0 + n4 * 4);
            }
        }
    };

    float acc[4][8][4];
    #pragma unroll
    for (int a = 0; a < 4; a++)
        #pragma unroll
        for (int b = 0; b < 8; b++)
            #pragma unroll
            for (int c = 0; c < 4; c++) acc[a][b][c] = 0.f;

    LOAD(0, 0); cpa_commit();
    if (nIt > 1) LOAD(1, 1);
    cpa_commit();

    for (int it = 0; it < nIt; ++it) {
        if (it < nIt - 1) asm volatile("cp.async.wait_group 1;" ::: "memory");
        else              asm volatile("cp.async.wait_group 0;" ::: "memory");
        __syncthreads();
        const float* As = smem + (it % 3) * STG;
        const float* Bs = As + ASZ;
        #pragma unroll
        for (int ks = 0; ks < 32; ks += 8) {
            uint32_t af[4][4], bf[8][2];
            #pragma unroll
            for (int mt = 0; mt < 4; mt++) {
                int mb = wm * 64 + mt * 16;
                af[mt][0] = __float_as_uint(As[(mb + r    ) * LDA_S + ks + cq    ]);
                af[mt][1] = __float_as_uint(As[(mb + r + 8) * LDA_S + ks + cq    ]);
                af[mt][2] = __float_as_uint(As[(mb + r    ) * LDA_S + ks + cq + 4]);
                af[mt][3] = __float_as_uint(As[(mb + r + 8) * LDA_S + ks + cq + 4]);
            }
            #pragma unroll
            for (int nt = 0; nt < 8; nt++) {
                int nb = wn * 64 + nt * 8;
                bf[nt][0] = __float_as_uint(Bs[(ks + cq    ) * LDB_S + nb + r]);
                bf[nt][1] = __float_as_uint(Bs[(ks + cq + 4) * LDB_S + nb + r]);
            }
            #pragma unroll
            for (int mt = 0; mt < 4; mt++)
                #pragma unroll
                for (int nt = 0; nt < 8; nt++)
                    mma8(acc[mt][nt], af[mt], bf[nt]);
        }
        if (it + 2 < nIt) { LOAD(it + 2, (it + 2) % 3); cpa_commit(); }
    }

    #pragma unroll
    for (int mt = 0; mt < 4; mt++)
        #pragma unroll
        for (int nt = 0; nt < 8; nt++) {
            int gm = m0 + wm * 64 + mt * 16 + r;
            int gn = n0 + wn * 64 + nt * 8 + cq * 2;
            #pragma unroll
            for (int half = 0; half < 2; half++) {
                long idx = (long)(gm + half * 8) * ldc + gn;
                float v0 = alpha * acc[mt][nt][half * 2];
                float v1 = alpha * acc[mt][nt][half * 2 + 1];
                if (beta != 0.f) {
                    float2 old = *(float2*)(C + idx);
                    v0 += beta * old.x; v1 += beta * old.y;
                }
                if (CVTO) { v0 = cvtf(v0); v1 = cvtf(v1); }
                *(float2*)(C + idx) = make_float2(v0, v1);
            }
        }
}

// ===== SIMT GEMM (LoRA shapes) =====
#define BMs 64
#define BNs 64
#define BKs 16
template<bool TB>
__global__ void gemm_kernel(const float* __restrict__ A, const float* __restrict__ B,
                            float* __restrict__ C, int M, int N, int K,
                            int lda, int ldb, int ldc, float alpha, float beta, int docvt) {
    __shared__ float As[BKs][BMs + 1];
    __shared__ float Bs[BKs][BNs + 1];
    int tid = threadIdx.x;
    int tx = tid % 16, ty = tid / 16;
    int m0 = blockIdx.y * BMs, n0 = blockIdx.x * BNs;
    float acc[4][4] = {};
    for (int k0 = 0; k0 < K; k0 += BKs) {
        {
            int kk = tid % 16, mrel = tid / 16;
            #pragma unroll
            for (int i = 0; i < 4; i++) {
                int m = mrel + i * 16, gm = m0 + m;
                As[kk][m] = (gm < M) ? A[(long)gm * lda + k0 + kk] : 0.f;
            }
        }
        if (!TB) {
            int n = tid % 64, kk0 = tid / 64;
            #pragma unroll
            for (int i = 0; i < 4; i++) {
                int kk = kk0 + i * 4, gn = n0 + n;
                Bs[kk][n] = (gn < N) ? B[(long)(k0 + kk) * ldb + gn] : 0.f;
            }
        } else {
            int kk = tid % 16, nrel = tid / 16;
            #pragma unroll
            for (int i = 0; i < 4; i++) {
                int n = nrel + i * 16, gn = n0 + n;
                Bs[kk][n] = (gn < N) ? B[(long)gn * ldb + k0 + kk] : 0.f;
            }
        }
        __syncthreads();
        #pragma unroll
        for (int kk = 0; kk < BKs; kk++) {
            float ra[4], rb[4];
            #pragma unroll
            for (int i = 0; i < 4; i++) ra[i] = As[kk][ty + 16 * i];
            #pragma unroll
            for (int j = 0; j < 4; j++) rb[j] = Bs[kk][tx + 16 * j];
            #pragma unroll
            for (int i = 0; i < 4; i++)
                #pragma unroll
                for (int j = 0; j < 4; j++)
                    acc[i][j] += ra[i] * rb[j];
        }
        __syncthreads();
    }
    #pragma unroll
    for (int i = 0; i < 4; i++) {
        int gm = m0 + ty + 16 * i;
        if (gm >= M) continue;
        #pragma unroll
        for (int j = 0; j < 4; j++) {
            int gn = n0 + tx + 16 * j;
            if (gn >= N) continue;
            long idx = (long)gm * ldc + gn;
            float prev = (beta != 0.f) ? beta * C[idx] : 0.f;
            float v = alpha * acc[i][j] + prev;
            C[idx] = docvt ? cvtf(v) : v;
        }
    }
}

static void sgemm(const float* A, const float* B, float* C, int M, int N, int K,
                  int lda, int ldb, int ldc, float alpha, float beta, bool tb, int docvt) {
    dim3 grid((N + BNs - 1) / BNs, (M + BMs - 1) / BMs);
    if (tb) gemm_kernel<true ><<<grid, 256>>>(A, B, C, M, N, K, lda, ldb, ldc, alpha, beta, docvt);
    else    gemm_kernel<false><<<grid, 256>>>(A, B, C, M, N, K, lda, ldb, ldc, alpha, beta, docvt);
}

template<int BN_, bool CVTO>
static void tg_launch(const float* A, const float* B, float* C, int M, int N, int K,
                      int lda, int ldb, int ldc, float alpha, float beta) {
    dim3 grid(N / BN_, M / 128);
    int smem = 3 * (128*36 + 32*(BN_+8)) * 4;
    cudaFuncSetAttribute(tc_gemm_kernel<BN_, CVTO>, cudaFuncAttributeMaxDynamicSharedMemorySize, smem);
    tc_gemm_kernel<BN_, CVTO><<<grid, BN_, smem>>>(A, B, C, M, N, K, lda, ldb, ldc, alpha, beta);
}

static void tgemm(const float* A, const float* B, float* C, int M, int N, int K,
                  int lda, int ldb, int ldc, float alpha, float beta, bool cvto) {
    if (N % 256 == 0) {
        if (cvto) tg_launch<256, true >(A, B, C, M, N, K, lda, ldb, ldc, alpha, beta);
        else      tg_launch<256, false>(A, B, C, M, N, K, lda, ldb, ldc, alpha, beta);
    } else {
        if (cvto) tg_launch<128, true >(A, B, C, M, N, K, lda, ldb, ldc, alpha, beta);
        else      tg_launch<128, false>(A, B, C, M, N, K, lda, ldb, ldc, alpha, beta);
    }
}

extern "C" void kernel_launch(void* const* d_in, const int* in_sizes, int n_in,
                              void* d_out, int out_size) {
    const int*   ids = (const int*)  d_in[0];
    const float* emb = (const float*)d_in[1];
    const float* Wq  = (const float*)d_in[2];
    const float* Wk  = (const float*)d_in[3];
    const float* Wv  = (const float*)d_in[4];
    const float* Wo  = (const float*)d_in[5];
    const float* W1  = (const float*)d_in[6];
    const float* W2  = (const float*)d_in[7];
    const float* ln1 = (const float*)d_in[8];
    const float* ln2 = (const float*)d_in[9];
    const float* lnf = (const float*)d_in[10];
    const float* lmh = (const float*)d_in[11];
    const float* Aq0 = (const float*)d_in[12];
    const float* Av0 = (const float*)d_in[14];
    const float* Bq  = (const float*)d_in[17];
    const float* Bv  = (const float*)d_in[19];
    float* out = (float*)d_out;

    float *x2, *h2, *qkv2, *o2, *u2, *t, *wcat, *woc, *w1c, *w2c, *lmc;
    cudaGetSymbolAddress((void**)&x2,   g_x2);
    cudaGetSymbolAddress((void**)&h2,   g_h2);
    cudaGetSymbolAddress((void**)&qkv2, g_qkv2);
    cudaGetSymbolAddress((void**)&o2,   g_o2);
    cudaGetSymbolAddress((void**)&u2,   g_u2);
    cudaGetSymbolAddress((void**)&t,    g_t);
    cudaGetSymbolAddress((void**)&wcat, g_wcat);
    cudaGetSymbolAddress((void**)&woc,  g_woc);
    cudaGetSymbolAddress((void**)&w1c,  g_w1c);
    cudaGetSymbolAddress((void**)&w2c,  g_w2c);
    cudaGetSymbolAddress((void**)&lmc,  g_lmc);

    float* x  = x2;  float* dx = x2 + (long)MM*DD;
    float* h  = h2;  float* dh = h2 + (long)MM*DD;
    const long PRJ = (long)MM * 3*DD;
    int at_smem = AT_FLOATS * 4;
    cudaFuncSetAttribute(attn_jvp_kernel, cudaFuncAttributeMaxDynamicSharedMemorySize, at_smem);

    embed_kernel<<<(MM * DD) / 256, 256>>>(ids, emb, x, dx);
    cvtcopy_kernel<<<((long)DD * VV / 4) / 256, 256>>>(lmh, lmc);

    for (int l = 0; l < LL; l++) {
        const float* Aq0l = Aq0 + (long)l * RR * DD;
        const float* Av0l = Av0 + (long)l * RR * DD;
        const float* Bql  = Bq  + (long)l * DD * RR;
        const float* Bvl  = Bv  + (long)l * DD * RR;
        float lbeta = (l == 0) ? 0.f : 1.f;

        catw_kernel<<<(DD * DD) / 256, 256>>>(Wq + (long)l*DD*DD, Wk + (long)l*DD*DD,
                                              Wv + (long)l*DD*DD, wcat);
        cvtcopy_kernel<<<((long)DD * DD / 4) / 256, 256>>>(Wo + (long)l*DD*DD, woc);
        cvtcopy_kernel<<<((long)DD * FFD / 4) / 256, 256>>>(W1 + (long)l*DD*FFD, w1c);
        cvtcopy_kernel<<<((long)FFD * DD / 4) / 256, 256>>>(W2 + (long)l*FFD*DD, w2c);

        rms_jvp_kernel<<<MM, 256>>>(x, dx, ln1 + (long)l * DD, h, dh);

        if (l == 0)
            tgemm(h2, wcat, qkv2,   MM, 3*DD, DD, DD, 3*DD, 3*DD, 1.f, 0.f, true);
        else
            tgemm(h2, wcat, qkv2, 2*MM, 3*DD, DD, DD, 3*DD, 3*DD, 1.f, 0.f, true);

        sgemm(h, Aq0l, t, MM, RR, DD, DD, DD, RR, 1.f, 0.f, true, 0);
        sgemm(t, Bql, qkv2 + PRJ,        MM, DD, RR, RR, RR, 3*DD, LORA_SCALE, lbeta, true, 1);
        sgemm(h, Av0l, t, MM, RR, DD, DD, DD, RR, 1.f, 0.f, true, 0);
        sgemm(t, Bvl, qkv2 + PRJ + 2*DD, MM, DD, RR, RR, RR, 3*DD, LORA_SCALE, lbeta, true, 1);

        attn_jvp_kernel<<<dim3(16, BB*HH), 256, at_smem>>>(qkv2, o2, o2 + (long)MM*DD, l > 0);

        tgemm(o2, woc, x2, 2*MM, DD, DD, DD, DD, DD, 1.f, 1.f, false);

        rms_jvp_kernel<<<MM, 256>>>(x, dx, ln2 + (long)l * DD, h, dh);
        tgemm(h2, w1c, u2, 2*MM, FFD, DD, DD, FFD, FFD, 1.f, 0.f, false);
        gelu_jvp_kernel<<<(MM * FFD) / 256, 256>>>(u2, u2 + (long)MM*FFD);
        tgemm(u2, w2c, x2, 2*MM, DD, FFD, FFD, DD, DD, 1.f, 1.f, false);
    }

    rms_final_kernel<<<MM, 256>>>(x, dx, lnf, h);
    tgemm(h, lmc, out, MM, VV, DD, DD, VV, VV, 1.f, 0.f, false);
}

// round 10
// speedup vs baseline: 1.4901x; 1.4901x over previous
#include <cuda_runtime.h>
#include <cuda_fp16.h>
#include <math.h>
#include <stdint.h>

#define LL 2
#define BB 2
#define SS 1024
#define DD 1024
#define HH 16
#define HDD 64
#define FFD 4096
#define VV 32000
#define RR 16
#define MM (BB*SS)
#define LORA_SCALE 2.0f
#define EPSV 1e-6f

__device__ float  g_x2  [2L*MM*DD];
__device__ __half g_h2  [2L*MM*DD];
__device__ float  g_qkv2[2L*MM*3*DD];
__device__ __half g_o2  [2L*MM*DD];
__device__ __half g_u2  [2L*MM*FFD];
__device__ float  g_t   [MM*RR];
__device__ __half g_wcat[3*DD*DD];   // [3DD][DD]  (transposed: row n, col k)
__device__ __half g_woc [DD*DD];     // [DD][DD]
__device__ __half g_w1c [FFD*DD];    // [FFD][DD]
__device__ __half g_w2c [DD*FFD];    // [DD][FFD]
__device__ __half g_lmc [VV*DD];     // [VV][DD]

__device__ __forceinline__ float blk_sum(float v, float* sm) {
    int tid = threadIdx.x;
    sm[tid] = v; __syncthreads();
    for (int s = 128; s > 0; s >>= 1) { if (tid < s) sm[tid] += sm[tid + s]; __syncthreads(); }
    float r = sm[0]; __syncthreads(); return r;
}
__device__ __forceinline__ float cvtf(float x) {
    uint32_t u; asm("cvt.rna.tf32.f32 %0, %1;" : "=r"(u) : "f"(x));
    return __uint_as_float(u);
}
__device__ __forceinline__ void cpa16(void* dst, const void* src) {
    uint32_t d = (uint32_t)__cvta_generic_to_shared(dst);
    asm volatile("cp.async.cg.shared.global [%0], [%1], 16;" :: "r"(d), "l"(src));
}
__device__ __forceinline__ void cpa_commit() { asm volatile("cp.async.commit_group;" ::: "memory"); }
__device__ __forceinline__ void cpa_wait0()  { asm volatile("cp.async.wait_group 0;" ::: "memory"); }
__device__ __forceinline__ float fast_tanh(float x) {
    float e = __expf(2.f * x);
    return 1.f - 2.f / (e + 1.f);
}
__device__ __forceinline__ void mma8(float* c, const uint32_t* a, const uint32_t* b) {
    asm volatile(
        "mma.sync.aligned.m16n8k8.row.col.f32.tf32.tf32.f32 "
        "{%0,%1,%2,%3}, {%4,%5,%6,%7}, {%8,%9}, {%0,%1,%2,%3};"
        : "+f"(c[0]), "+f"(c[1]), "+f"(c[2]), "+f"(c[3])
        : "r"(a[0]), "r"(a[1]), "r"(a[2]), "r"(a[3]), "r"(b[0]), "r"(b[1]));
}
__device__ __forceinline__ void mma16h(float* c, const uint32_t* a, const uint32_t* b) {
    asm volatile(
        "mma.sync.aligned.m16n8k16.row.col.f32.f16.f16.f32 "
        "{%0,%1,%2,%3}, {%4,%5,%6,%7}, {%8,%9}, {%0,%1,%2,%3};"
        : "+f"(c[0]), "+f"(c[1]), "+f"(c[2]), "+f"(c[3])
        : "r"(a[0]), "r"(a[1]), "r"(a[2]), "r"(a[3]), "r"(b[0]), "r"(b[1]));
}

__global__ void embed_kernel(const int* __restrict__ ids, const float* __restrict__ emb,
                             float* __restrict__ x, float* __restrict__ dx) {
    long i = (long)blockIdx.x * blockDim.x + threadIdx.x;
    int col = (int)(i % DD), row = (int)(i / DD);
    x[i]  = emb[(long)ids[row] * DD + col];
    dx[i] = 0.f;
}

// transpose + fp16 convert: in float [K][N] -> out half [N][K]. block (32,8)
__global__ void transT_kernel(const float* __restrict__ in, __half* __restrict__ out,
                              int K, int N) {
    __shared__ float tile[32][33];
    int n0 = blockIdx.x * 32, k0 = blockIdx.y * 32;
    int tx = threadIdx.x, ty = threadIdx.y;
    #pragma unroll
    for (int i = 0; i < 32; i += 8)
        tile[ty + i][tx] = in[(long)(k0 + ty + i) * N + n0 + tx];
    __syncthreads();
    #pragma unroll
    for (int i = 0; i < 32; i += 8)
        out[(long)(n0 + ty + i) * K + k0 + tx] = __float2half_rn(tile[tx][ty + i]);
}

// concat Wq|Wk|Wv transposed: out[j][d] half, j in [0,3DD)
__global__ void catwT_kernel(const float* __restrict__ Wq, const float* __restrict__ Wk,
                             const float* __restrict__ Wv, __half* __restrict__ out) {
    __shared__ float tile[32][33];
    int j0 = blockIdx.x * 32, d0 = blockIdx.y * 32;
    const float* src = (j0 < DD) ? Wq : (j0 < 2*DD ? Wk : Wv);
    int jb = j0 % DD;
    int tx = threadIdx.x, ty = threadIdx.y;
    #pragma unroll
    for (int i = 0; i < 32; i += 8)
        tile[ty + i][tx] = src[(long)(d0 + ty + i) * DD + jb + tx];
    __syncthreads();
    #pragma unroll
    for (int i = 0; i < 32; i += 8)
        out[(long)(j0 + ty + i) * DD + d0 + tx] = __float2half_rn(tile[tx][ty + i]);
}

__global__ void rms_jvp_kernel(const float* __restrict__ x, const float* __restrict__ dx,
                               const float* __restrict__ g,
                               __half* __restrict__ h, __half* __restrict__ dh) {
    __shared__ float sm[256];
    int row = blockIdx.x, tid = threadIdx.x;
    const float* xr  = x  + (long)row * DD;
    const float* dxr = dx + (long)row * DD;
    __half* hr  = h  + (long)row * DD;
    __half* dhr = dh + (long)row * DD;
    float s2 = 0.f, sxd = 0.f;
    for (int i = tid; i < DD; i += 256) { float xv = xr[i], dv = dxr[i]; s2 += xv*xv; sxd += xv*dv; }
    s2  = blk_sum(s2,  sm);
    sxd = blk_sum(sxd, sm);
    float r = rsqrtf(s2 / (float)DD + EPSV);
    float c = (sxd / (float)DD) * r * r * r;
    for (int i = tid; i < DD; i += 256) {
        float xv = xr[i], dv = dxr[i], gv = g[i];
        hr[i]  = __float2half_rn(xv * gv * r);
        dhr[i] = __float2half_rn(gv * (dv * r - xv * c));
    }
}

__global__ void rms_final_kernel(const float* __restrict__ x, const float* __restrict__ dx,
                                 const float* __restrict__ g, __half* __restrict__ out) {
    __shared__ float sm[256];
    int row = blockIdx.x, tid = threadIdx.x;
    const float* xr  = x  + (long)row * DD;
    const float* dxr = dx + (long)row * DD;
    __half* orow = out + (long)row * DD;
    float s2 = 0.f, sxd = 0.f;
    for (int i = tid; i < DD; i += 256) { float xv = xr[i], dv = dxr[i]; s2 += xv*xv; sxd += xv*dv; }
    s2  = blk_sum(s2,  sm);
    sxd = blk_sum(sxd, sm);
    float r = rsqrtf(s2 / (float)DD + EPSV);
    float c = (sxd / (float)DD) * r * r * r;
    for (int i = tid; i < DD; i += 256) {
        float xv = xr[i], dv = dxr[i], gv = g[i];
        orow[i] = __float2half_rn(xv * gv * r + gv * (dv * r - xv * c));
    }
}

__global__ void gelu_jvp_kernel(__half* __restrict__ u, __half* __restrict__ du) {
    long i = (long)blockIdx.x * blockDim.x + threadIdx.x;
    float x = __half2float(u[i]), d = __half2float(du[i]);
    const float c0 = 0.7978845608028654f, c1 = 0.044715f;
    float x2 = x * x;
    float t  = fast_tanh(c0 * (x + c1 * x * x2));
    float gl = 0.5f * x * (1.f + t);
    float dg = 0.5f * (1.f + t) + 0.5f * x * (1.f - t*t) * c0 * (1.f + 3.f * c1 * x2);
    u[i]  = __float2half_rn(gl);
    du[i] = __float2half_rn(dg * d);
}

// ===== fused attention JVP (tf32 internals; reads fp32 qkv2, writes half o2) =====
#define AT_LD 68
#define AT_LDV 72
#define AT_T68 (64*AT_LD)
#define AT_T72 (64*AT_LDV)
#define SQ    0
#define SDQ   (SQ + AT_T68)
#define SK    (SDQ + AT_T68)
#define SDK   (SK + 2*AT_T68)
#define SV    (SDK + 2*AT_T68)
#define SDV   (SV + 2*AT_T72)
#define SP    (SDV + 2*AT_T72)
#define SPDS  (SP + AT_T68)
#define SLRED (SPDS + AT_T68)
#define STRED (SLRED + 256)
#define SLRUN (STRED + 256)
#define STRUN (SLRUN + 64)
#define AT_FLOATS (STRUN + 64)

__global__ __launch_bounds__(256)
void attn_jvp_kernel(const float* __restrict__ qkv, __half* __restrict__ o2p,
                     __half* __restrict__ o2t, int has_dk)
{
    extern __shared__ float smem[];
    int mb = 15 - blockIdx.x;
    int bh = blockIdx.y;
    int b = bh >> 4, hh = bh & 15;
    int m0 = mb * 64;
    int nc = mb + 1;
    const long RW = 3 * DD;
    const long PRJ = (long)MM * 3 * DD;
    const float* qp = qkv + (long)(b*SS + m0) * RW + hh * HDD;
    int tid = threadIdx.x;
    int lane = tid & 31, wid = tid >> 5;
    int wm = wid >> 2, wn = wid & 3;
    int r = lane >> 2, cq = lane & 3;

    if (tid < 64) { smem[SLRUN + tid] = 0.f; smem[STRUN + tid] = 0.f; }

    {
        const float* kp = qkv + (long)(b*SS) * RW + DD + hh * HDD;
        const float* vp = qkv + (long)(b*SS) * RW + 2*DD + hh * HDD;
        #pragma unroll
        for (int i = 0; i < 4; i++) {
            int idx = tid + i * 256; int row = idx >> 4; int c4 = idx & 15;
            cpa16(&smem[SQ  + row*AT_LD  + c4*4], qp + (long)row * RW + c4*4);
            cpa16(&smem[SDQ + row*AT_LD  + c4*4], qp + PRJ + (long)row * RW + c4*4);
            cpa16(&smem[SK  + row*AT_LD  + c4*4], kp + (long)row * RW + c4*4);
            cpa16(&smem[SV  + row*AT_LDV + c4*4], vp + (long)row * RW + c4*4);
            cpa16(&smem[SDV + row*AT_LDV + c4*4], vp + PRJ + (long)row * RW + c4*4);
            if (has_dk)
                cpa16(&smem[SDK + row*AT_LD + c4*4], kp + PRJ + (long)row * RW + c4*4);
        }
        cpa_commit();
    }

    float o1[2][2][4] = {}, o2a[2][2][4] = {}, o3[2][2][4] = {};

    for (int ic = 0; ic < nc; ic++) {
        cpa_wait0();
        __syncthreads();
        int cur = ic & 1;
        if (ic + 1 < nc) {
            int nxt = (ic + 1) & 1;
            int kb = (ic + 1) * 64;
            const float* kp = qkv + (long)(b*SS + kb) * RW + DD + hh * HDD;
            const float* vp = qkv + (long)(b*SS + kb) * RW + 2*DD + hh * HDD;
            #pragma unroll
            for (int i = 0; i < 4; i++) {
                int idx = tid + i * 256; int row = idx >> 4; int c4 = idx & 15;
                cpa16(&smem[SK  + nxt*AT_T68 + row*AT_LD  + c4*4], kp + (long)row * RW + c4*4);
                cpa16(&smem[SV  + nxt*AT_T72 + row*AT_LDV + c4*4], vp + (long)row * RW + c4*4);
                cpa16(&smem[SDV + nxt*AT_T72 + row*AT_LDV + c4*4], vp + PRJ + (long)row * RW + c4*4);
                if (has_dk)
                    cpa16(&smem[SDK + nxt*AT_T68 + row*AT_LD + c4*4], kp + PRJ + (long)row * RW + c4*4);
            }
            cpa_commit();
        }
        const float* Ks  = smem + SK  + cur * AT_T68;
        const float* dKs = smem + SDK + cur * AT_T68;
        const float* Vs  = smem + SV  + cur * AT_T72;
        const float* dVs = smem + SDV + cur * AT_T72;

        float sacc[2][2][4] = {}, dsacc[2][2][4] = {};
        #pragma unroll
        for (int ks = 0; ks < 64; ks += 8) {
            uint32_t aq[2][4], adq[2][4], bk[2][2], bdk[2][2];
            #pragma unroll
            for (int mt = 0; mt < 2; mt++) {
                int base = (wm*32 + mt*16 + r) * AT_LD + ks + cq;
                aq[mt][0]  = __float_as_uint(smem[SQ  + base]);
                aq[mt][1]  = __float_as_uint(smem[SQ  + base + 8*AT_LD]);
                aq[mt][2]  = __float_as_uint(smem[SQ  + base + 4]);
                aq[mt][3]  = __float_as_uint(smem[SQ  + base + 8*AT_LD + 4]);
                adq[mt][0] = __float_as_uint(smem[SDQ + base]);
                adq[mt][1] = __float_as_uint(smem[SDQ + base + 8*AT_LD]);
                adq[mt][2] = __float_as_uint(smem[SDQ + base + 4]);
                adq[mt][3] = __float_as_uint(smem[SDQ + base + 8*AT_LD + 4]);
            }
            #pragma unroll
            for (int nt = 0; nt < 2; nt++) {
                int boff = (wn*16 + nt*8 + r) * AT_LD + ks + cq;
                bk[nt][0] = __float_as_uint(Ks[boff]);
                bk[nt][1] = __float_as_uint(Ks[boff + 4]);
                if (has_dk) {
                    bdk[nt][0] = __float_as_uint(dKs[boff]);
                    bdk[nt][1] = __float_as_uint(dKs[boff + 4]);
                }
            }
            #pragma unroll
            for (int mt = 0; mt < 2; mt++)
                #pragma unroll
                for (int nt = 0; nt < 2; nt++) {
                    mma8(sacc[mt][nt], aq[mt], bk[nt]);
                    mma8(dsacc[mt][nt], adq[mt], bk[nt]);
                    if (has_dk) mma8(dsacc[mt][nt], aq[mt], bdk[nt]);
                }
        }

        int diag = (ic == mb);
        float lp[2][2] = {}, tp[2][2] = {};
        #pragma unroll
        for (int mt = 0; mt < 2; mt++)
            #pragma unroll
            for (int nt = 0; nt < 2; nt++)
                #pragma unroll
                for (int j = 0; j < 4; j++) {
                    int row = wm*32 + mt*16 + r + (j >> 1) * 8;
                    int col = wn*16 + nt*8 + cq*2 + (j & 1);
                    float s  = sacc[mt][nt][j]  * 0.125f;
                    float ds = dsacc[mt][nt][j] * 0.125f;
                    float pv = (diag && col > row) ? 0.f : cvtf(__expf(s));
                    float pd = cvtf(pv * ds);
                    smem[SP   + row*AT_LD + col] = pv;
                    smem[SPDS + row*AT_LD + col] = pd;
                    lp[mt][j>>1] += pv;
                    tp[mt][j>>1] += pd;
                }
        #pragma unroll
        for (int mt = 0; mt < 2; mt++)
            #pragma unroll
            for (int hf = 0; hf < 2; hf++) {
                float lv = lp[mt][hf], tv = tp[mt][hf];
                lv += __shfl_xor_sync(0xffffffff, lv, 1);
                lv += __shfl_xor_sync(0xffffffff, lv, 2);
                tv += __shfl_xor_sync(0xffffffff, tv, 1);
                tv += __shfl_xor_sync(0xffffffff, tv, 2);
                if (cq == 0) {
                    int row = wm*32 + mt*16 + r + hf*8;
                    smem[SLRED + row*4 + wn] = lv;
                    smem[STRED + row*4 + wn] = tv;
                }
            }
        __syncthreads();
        if (tid < 64) {
            smem[SLRUN + tid] += smem[SLRED + tid*4] + smem[SLRED + tid*4+1]
                               + smem[SLRED + tid*4+2] + smem[SLRED + tid*4+3];
            smem[STRUN + tid] += smem[STRED + tid*4] + smem[STRED + tid*4+1]
                               + smem[STRED + tid*4+2] + smem[STRED + tid*4+3];
        }

        #pragma unroll
        for (int ks = 0; ks < 64; ks += 8) {
            uint32_t ap[2][4], apd[2][4], bv[2][2], bdv[2][2];
            #pragma unroll
            for (int mt = 0; mt < 2; mt++) {
                int base = (wm*32 + mt*16 + r) * AT_LD + ks + cq;
                ap[mt][0]  = __float_as_uint(smem[SP   + base]);
                ap[mt][1]  = __float_as_uint(smem[SP   + base + 8*AT_LD]);
                ap[mt][2]  = __float_as_uint(smem[SP   + base + 4]);
                ap[mt][3]  = __float_as_uint(smem[SP   + base + 8*AT_LD + 4]);
                apd[mt][0] = __float_as_uint(smem[SPDS + base]);
                apd[mt][1] = __float_as_uint(smem[SPDS + base + 8*AT_LD]);
                apd[mt][2] = __float_as_uint(smem[SPDS + base + 4]);
                apd[mt][3] = __float_as_uint(smem[SPDS + base + 8*AT_LD + 4]);
            }
            #pragma unroll
            for (int nt = 0; nt < 2; nt++) {
                int nb = wn*16 + nt*8;
                bv[nt][0]  = __float_as_uint(Vs[(ks + cq) * AT_LDV + nb + r]);
                bv[nt][1]  = __float_as_uint(Vs[(ks + cq + 4) * AT_LDV + nb + r]);
                bdv[nt][0] = __float_as_uint(dVs[(ks + cq) * AT_LDV + nb + r]);
                bdv[nt][1] = __float_as_uint(dVs[(ks + cq + 4) * AT_LDV + nb + r]);
            }
            #pragma unroll
            for (int mt = 0; mt < 2; mt++)
                #pragma unroll
                for (int nt = 0; nt < 2; nt++) {
                    mma8(o1[mt][nt],  ap[mt],  bv[nt]);
                    mma8(o2a[mt][nt], apd[mt], bv[nt]);
                    mma8(o3[mt][nt],  ap[mt],  bdv[nt]);
                }
        }
    }

    __syncthreads();
    #pragma unroll
    for (int mt = 0; mt < 2; mt++)
        #pragma unroll
        for (int nt = 0; nt < 2; nt++)
            #pragma unroll
            for (int hf = 0; hf < 2; hf++) {
                int lrow = wm*32 + mt*16 + r + hf*8;
                float inv = 1.f / smem[SLRUN + lrow];
                float tf = smem[STRUN + lrow] * inv;
                int j0 = hf * 2;
                float oa = o1[mt][nt][j0]   * inv;
                float ob = o1[mt][nt][j0+1] * inv;
                float da = (o2a[mt][nt][j0]   - tf * o1[mt][nt][j0])   * inv + o3[mt][nt][j0]   * inv;
                float db = (o2a[mt][nt][j0+1] - tf * o1[mt][nt][j0+1]) * inv + o3[mt][nt][j0+1] * inv;
                long idx = (long)(b*SS + m0 + lrow) * DD + hh * HDD + wn*16 + nt*8 + cq*2;
                *(half2*)(o2p + idx) = __floats2half2_rn(oa, ob);
                *(half2*)(o2t + idx) = __floats2half2_rn(da, db);
            }
}

// ===== FP16 tensor-core GEMM: 128x128x64 CTA tile, 64x32 warp tile, 3-stage cp.async =====
// A: half [M][K] row-major. B: half [N][K] row-major (pre-transposed weight).
// C: float (optional tf32 round, optional beta=1) or half (beta=0).
template<bool CHALF, bool CVTO>
__global__ __launch_bounds__(256, 2)
void hgemm_kernel(const __half* __restrict__ A, const __half* __restrict__ B,
                  void* __restrict__ Cv, int M, int N, int K,
                  int lda, int ldb, int ldc, float beta)
{
    extern __shared__ __half hsm[];
    constexpr int LD = 72;                 // halfs per row (64 + 8 pad)
    constexpr int ASZ = 128 * LD;
    constexpr int STG = 2 * ASZ;           // A tile + B tile
    int m0 = blockIdx.y * 128, n0 = blockIdx.x * 128;
    int nIt = K >> 6;
    int tid = threadIdx.x;
    int lane = tid & 31, wid = tid >> 5;
    int wm = wid >> 2, wn = wid & 3;
    int r = lane >> 2, cq = lane & 3;
    int c8 = tid & 7, mr = tid >> 3;

    auto LOAD = [&](int kt, int st) {
        __half* As = hsm + st * STG;
        __half* Bs = As + ASZ;
        int k0 = kt * 64;
        #pragma unroll
        for (int i = 0; i < 4; i++) {
            int m = mr + i * 32;
            cpa16(&As[m * LD + c8 * 8], A + (long)(m0 + m) * lda + k0 + c8 * 8);
            cpa16(&Bs[m * LD + c8 * 8], B + (long)(n0 + m) * ldb + k0 + c8 * 8);
        }
    };

    float acc[4][4][4] = {};

    LOAD(0, 0); cpa_commit();
    if (nIt > 1) LOAD(1, 1);
    cpa_commit();

    for (int it = 0; it < nIt; ++it) {
        if (it < nIt - 1) asm volatile("cp.async.wait_group 1;" ::: "memory");
        else              asm volatile("cp.async.wait_group 0;" ::: "memory");
        __syncthreads();
        const __half* As = hsm + (it % 3) * STG;
        const __half* Bs = As + ASZ;
        #pragma unroll
        for (int ks = 0; ks < 64; ks += 16) {
            uint32_t af[4][4], bf[4][2];
            #pragma unroll
            for (int mt = 0; mt < 4; mt++) {
                int base = (wm * 64 + mt * 16 + r) * LD + ks + 2 * cq;
                af[mt][0] = *(const uint32_t*)&As[base];
                af[mt][1] = *(const uint32_t*)&As[base + 8 * LD];
                af[mt][2] = *(const uint32_t*)&As[base + 8];
                af[mt][3] = *(const uint32_t*)&As[base + 8 * LD + 8];
            }
            #pragma unroll
            for (int nt = 0; nt < 4; nt++) {
                int bb = (wn * 32 + nt * 8 + r) * LD + ks + 2 * cq;
                bf[nt][0] = *(const uint32_t*)&Bs[bb];
                bf[nt][1] = *(const uint32_t*)&Bs[bb + 8];
            }
            #pragma unroll
            for (int mt = 0; mt < 4; mt++)
                #pragma unroll
                for (int nt = 0; nt < 4; nt++)
                    mma16h(acc[mt][nt], af[mt], bf[nt]);
        }
        if (it + 2 < nIt) { LOAD(it + 2, (it + 2) % 3); cpa_commit(); }
    }

    #pragma unroll
    for (int mt = 0; mt < 4; mt++)
        #pragma unroll
        for (int nt = 0; nt < 4; nt++) {
            int gm = m0 + wm * 64 + mt * 16 + r;
            int gn = n0 + wn * 32 + nt * 8 + cq * 2;
            #pragma unroll
            for (int hf = 0; hf < 2; hf++) {
                long idx = (long)(gm + hf * 8) * ldc + gn;
                float v0 = acc[mt][nt][hf * 2];
                float v1 = acc[mt][nt][hf * 2 + 1];
                if (CHALF) {
                    *(half2*)((__half*)Cv + idx) = __floats2half2_rn(v0, v1);
                } else {
                    float* C = (float*)Cv;
                    if (beta != 0.f) { float2 o = *(float2*)(C + idx); v0 += o.x; v1 += o.y; }
                    if (CVTO) { v0 = cvtf(v0); v1 = cvtf(v1); }
                    *(float2*)(C + idx) = make_float2(v0, v1);
                }
            }
        }
}

// ===== SIMT GEMM (LoRA shapes), A may be half =====
#define BMs 64
#define BNs 64
#define BKs 16
template<bool TB, typename AT>
__global__ void gemm_kernel(const AT* __restrict__ A, const float* __restrict__ B,
                            float* __restrict__ C, int M, int N, int K,
                            int lda, int ldb, int ldc, float alpha, float beta, int docvt) {
    __shared__ float As[BKs][BMs + 1];
    __shared__ float Bs[BKs][BNs + 1];
    int tid = threadIdx.x;
    int tx = tid % 16, ty = tid / 16;
    int m0 = blockIdx.y * BMs, n0 = blockIdx.x * BNs;
    float acc[4][4] = {};
    for (int k0 = 0; k0 < K; k0 += BKs) {
        {
            int kk = tid % 16, mrel = tid / 16;
            #pragma unroll
            for (int i = 0; i < 4; i++) {
                int m = mrel + i * 16, gm = m0 + m;
                As[kk][m] = (gm < M) ? (float)A[(long)gm * lda + k0 + kk] : 0.f;
            }
        }
        if (!TB) {
            int n = tid % 64, kk0 = tid / 64;
            #pragma unroll
            for (int i = 0; i < 4; i++) {
                int kk = kk0 + i * 4, gn = n0 + n;
                Bs[kk][n] = (gn < N) ? B[(long)(k0 + kk) * ldb + gn] : 0.f;
            }
        } else {
            int kk = tid % 16, nrel = tid / 16;
            #pragma unroll
            for (int i = 0; i < 4; i++) {
                int n = nrel + i * 16, gn = n0 + n;
                Bs[kk][n] = (gn < N) ? B[(long)gn * ldb + k0 + kk] : 0.f;
            }
        }
        __syncthreads();
        #pragma unroll
        for (int kk = 0; kk < BKs; kk++) {
            float ra[4], rb[4];
            #pragma unroll
            for (int i = 0; i < 4; i++) ra[i] = As[kk][ty + 16 * i];
            #pragma unroll
            for (int j = 0; j < 4; j++) rb[j] = Bs[kk][tx + 16 * j];
            #pragma unroll
            for (int i = 0; i < 4; i++)
                #pragma unroll
                for (int j = 0; j < 4; j++)
                    acc[i][j] += ra[i] * rb[j];
        }
        __syncthreads();
    }
    #pragma unroll
    for (int i = 0; i < 4; i++) {
        int gm = m0 + ty + 16 * i;
        if (gm >= M) continue;
        #pragma unroll
        for (int j = 0; j < 4; j++) {
            int gn = n0 + tx + 16 * j;
            if (gn >= N) continue;
            long idx = (long)gm * ldc + gn;
            float prev = (beta != 0.f) ? beta * C[idx] : 0.f;
            float v = alpha * acc[i][j] + prev;
            C[idx] = docvt ? cvtf(v) : v;
        }
    }
}

template<bool CHALF, bool CVTO>
static void hg_launch(const __half* A, const __half* B, void* C, int M, int N, int K,
                      int lda, int ldb, int ldc, float beta) {
    dim3 grid(N / 128, M / 128);
    int smem = 3 * 2 * 128 * 72 * (int)sizeof(__half);
    cudaFuncSetAttribute(hgemm_kernel<CHALF, CVTO>, cudaFuncAttributeMaxDynamicSharedMemorySize, smem);
    hgemm_kernel<CHALF, CVTO><<<grid, 256, smem>>>(A, B, C, M, N, K, lda, ldb, ldc, beta);
}

extern "C" void kernel_launch(void* const* d_in, const int* in_sizes, int n_in,
                              void* d_out, int out_size) {
    const int*   ids = (const int*)  d_in[0];
    const float* emb = (const float*)d_in[1];
    const float* Wq  = (const float*)d_in[2];
    const float* Wk  = (const float*)d_in[3];
    const float* Wv  = (const float*)d_in[4];
    const float* Wo  = (const float*)d_in[5];
    const float* W1  = (const float*)d_in[6];
    const float* W2  = (const float*)d_in[7];
    const float* ln1 = (const float*)d_in[8];
    const float* ln2 = (const float*)d_in[9];
    const float* lnf = (const float*)d_in[10];
    const float* lmh = (const float*)d_in[11];
    const float* Aq0 = (const float*)d_in[12];
    const float* Av0 = (const float*)d_in[14];
    const float* Bq  = (const float*)d_in[17];
    const float* Bv  = (const float*)d_in[19];
    float* out = (float*)d_out;

    float *x2, *qkv2, *t;
    __half *h2, *o2, *u2, *wcat, *woc, *w1c, *w2c, *lmc;
    cudaGetSymbolAddress((void**)&x2,   g_x2);
    cudaGetSymbolAddress((void**)&h2,   g_h2);
    cudaGetSymbolAddress((void**)&qkv2, g_qkv2);
    cudaGetSymbolAddress((void**)&o2,   g_o2);
    cudaGetSymbolAddress((void**)&u2,   g_u2);
    cudaGetSymbolAddress((void**)&t,    g_t);
    cudaGetSymbolAddress((void**)&wcat, g_wcat);
    cudaGetSymbolAddress((void**)&woc,  g_woc);
    cudaGetSymbolAddress((void**)&w1c,  g_w1c);
    cudaGetSymbolAddress((void**)&w2c,  g_w2c);
    cudaGetSymbolAddress((void**)&lmc,  g_lmc);

    float*  x  = x2;  float*  dx = x2 + (long)MM*DD;
    __half* h  = h2;  __half* dh = h2 + (long)MM*DD;
    const long PRJ = (long)MM * 3*DD;
    int at_smem = AT_FLOATS * 4;
    cudaFuncSetAttribute(attn_jvp_kernel, cudaFuncAttributeMaxDynamicSharedMemorySize, at_smem);

    embed_kernel<<<(MM * DD) / 256, 256>>>(ids, emb, x, dx);
    transT_kernel<<<dim3(VV/32, DD/32), dim3(32,8)>>>(lmh, lmc, DD, VV);

    for (int l = 0; l < LL; l++) {
        const float* Aq0l = Aq0 + (long)l * RR * DD;
        const float* Av0l = Av0 + (long)l * RR * DD;
        const float* Bql  = Bq  + (long)l * DD * RR;
        const float* Bvl  = Bv  + (long)l * DD * RR;
        float lbeta = (l == 0) ? 0.f : 1.f;

        catwT_kernel<<<dim3(3*DD/32, DD/32), dim3(32,8)>>>(Wq + (long)l*DD*DD,
                                                           Wk + (long)l*DD*DD,
                                                           Wv + (long)l*DD*DD, wcat);
        transT_kernel<<<dim3(DD/32,  DD/32),  dim3(32,8)>>>(Wo + (long)l*DD*DD,  woc, DD,  DD);
        transT_kernel<<<dim3(FFD/32, DD/32),  dim3(32,8)>>>(W1 + (long)l*DD*FFD, w1c, DD,  FFD);
        transT_kernel<<<dim3(DD/32,  FFD/32), dim3(32,8)>>>(W2 + (long)l*FFD*DD, w2c, FFD, DD);

        rms_jvp_kernel<<<MM, 256>>>(x, dx, ln1 + (long)l * DD, h, dh);

        // qkv projection (fp16 TC). l=0 tangent is pure LoRA.
        if (l == 0)
            hg_launch<false, true>(h2, wcat, qkv2,   MM, 3*DD, DD, DD, DD, 3*DD, 0.f);
        else
            hg_launch<false, true>(h2, wcat, qkv2, 2*MM, 3*DD, DD, DD, DD, 3*DD, 0.f);

        // LoRA tangents (SIMT, tiny)
        gemm_kernel<true, __half><<<dim3(1, MM/BMs), 256>>>(h, Aq0l, t, MM, RR, DD, DD, DD, RR, 1.f, 0.f, 0);
        gemm_kernel<true, float ><<<dim3(DD/BNs, MM/BMs), 256>>>(t, Bql, qkv2 + PRJ,
            MM, DD, RR, RR, RR, 3*DD, LORA_SCALE, lbeta, 1);
        gemm_kernel<true, __half><<<dim3(1, MM/BMs), 256>>>(h, Av0l, t, MM, RR, DD, DD, DD, RR, 1.f, 0.f, 0);
        gemm_kernel<true, float ><<<dim3(DD/BNs, MM/BMs), 256>>>(t, Bvl, qkv2 + PRJ + 2*DD,
            MM, DD, RR, RR, RR, 3*DD, LORA_SCALE, lbeta, 1);

        attn_jvp_kernel<<<dim3(16, BB*HH), 256, at_smem>>>(qkv2, o2, o2 + (long)MM*DD, l > 0);

        // residual: x2 += o2 @ Wo^T-stored
        hg_launch<false, false>(o2, woc, x2, 2*MM, DD, DD, DD, DD, DD, 1.f);

        rms_jvp_kernel<<<MM, 256>>>(x, dx, ln2 + (long)l * DD, h, dh);
        hg_launch<true, false>(h2, w1c, u2, 2*MM, FFD, DD, DD, DD, FFD, 0.f);
        gelu_jvp_kernel<<<(MM * FFD) / 256, 256>>>(u2, u2 + (long)MM*FFD);
        hg_launch<false, false>(u2, w2c, x2, 2*MM, DD, FFD, FFD, FFD, DD, 1.f);
    }

    rms_final_kernel<<<MM, 256>>>(x, dx, lnf, h);
    hg_launch<false, false>(h, lmc, out, MM, VV, DD, DD, DD, VV, 0.f);
}

// round 15
// speedup vs baseline: 1.4930x; 1.0020x over previous
#include <cuda_runtime.h>
#include <cuda_fp16.h>
#include <math.h>
#include <stdint.h>

#define LL 2
#define BB 2
#define SS 1024
#define DD 1024
#define HH 16
#define HDD 64
#define FFD 4096
#define VV 32000
#define RR 16
#define MM (BB*SS)
#define LORA_SCALE 2.0f
#define EPSV 1e-6f

__device__ float  g_x2  [2L*MM*DD];
__device__ __half g_h2  [2L*MM*DD];
__device__ float  g_qkv2[2L*MM*3*DD];
__device__ __half g_o2  [2L*MM*DD];
__device__ __half g_u2  [2L*MM*FFD];
__device__ float  g_t   [MM*RR];
__device__ __half g_wcat[3*DD*DD];
__device__ __half g_woc [DD*DD];
__device__ __half g_w1c [FFD*DD];
__device__ __half g_w2c [DD*FFD];
__device__ __half g_lmc [VV*DD];

__device__ __forceinline__ float blk_sum(float v, float* sm) {
    int tid = threadIdx.x;
    sm[tid] = v; __syncthreads();
    for (int s = 128; s > 0; s >>= 1) { if (tid < s) sm[tid] += sm[tid + s]; __syncthreads(); }
    float r = sm[0]; __syncthreads(); return r;
}
__device__ __forceinline__ float cvtf(float x) {
    uint32_t u; asm("cvt.rna.tf32.f32 %0, %1;" : "=r"(u) : "f"(x));
    return __uint_as_float(u);
}
__device__ __forceinline__ void cpa16(void* dst, const void* src) {
    uint32_t d = (uint32_t)__cvta_generic_to_shared(dst);
    asm volatile("cp.async.cg.shared.global [%0], [%1], 16;" :: "r"(d), "l"(src));
}
__device__ __forceinline__ void cpa_commit() { asm volatile("cp.async.commit_group;" ::: "memory"); }
__device__ __forceinline__ void cpa_wait0()  { asm volatile("cp.async.wait_group 0;" ::: "memory"); }
__device__ __forceinline__ float fast_tanh(float x) {
    float e = __expf(2.f * x);
    return 1.f - 2.f / (e + 1.f);
}
__device__ __forceinline__ void mma8(float* c, const uint32_t* a, const uint32_t* b) {
    asm volatile(
        "mma.sync.aligned.m16n8k8.row.col.f32.tf32.tf32.f32 "
        "{%0,%1,%2,%3}, {%4,%5,%6,%7}, {%8,%9}, {%0,%1,%2,%3};"
        : "+f"(c[0]), "+f"(c[1]), "+f"(c[2]), "+f"(c[3])
        : "r"(a[0]), "r"(a[1]), "r"(a[2]), "r"(a[3]), "r"(b[0]), "r"(b[1]));
}
__device__ __forceinline__ void mma16h(float* c, const uint32_t* a, const uint32_t* b) {
    asm volatile(
        "mma.sync.aligned.m16n8k16.row.col.f32.f16.f16.f32 "
        "{%0,%1,%2,%3}, {%4,%5,%6,%7}, {%8,%9}, {%0,%1,%2,%3};"
        : "+f"(c[0]), "+f"(c[1]), "+f"(c[2]), "+f"(c[3])
        : "r"(a[0]), "r"(a[1]), "r"(a[2]), "r"(a[3]), "r"(b[0]), "r"(b[1]));
}

__global__ void embed_kernel(const int* __restrict__ ids, const float* __restrict__ emb,
                             float* __restrict__ x, float* __restrict__ dx) {
    long i = (long)blockIdx.x * blockDim.x + threadIdx.x;
    int col = (int)(i % DD), row = (int)(i / DD);
    x[i]  = emb[(long)ids[row] * DD + col];
    dx[i] = 0.f;
}

__global__ void transT_kernel(const float* __restrict__ in, __half* __restrict__ out,
                              int K, int N) {
    __shared__ float tile[32][33];
    int n0 = blockIdx.x * 32, k0 = blockIdx.y * 32;
    int tx = threadIdx.x, ty = threadIdx.y;
    #pragma unroll
    for (int i = 0; i < 32; i += 8)
        tile[ty + i][tx] = in[(long)(k0 + ty + i) * N + n0 + tx];
    __syncthreads();
    #pragma unroll
    for (int i = 0; i < 32; i += 8)
        out[(long)(n0 + ty + i) * K + k0 + tx] = __float2half_rn(tile[tx][ty + i]);
}

__global__ void catwT_kernel(const float* __restrict__ Wq, const float* __restrict__ Wk,
                             const float* __restrict__ Wv, __half* __restrict__ out) {
    __shared__ float tile[32][33];
    int j0 = blockIdx.x * 32, d0 = blockIdx.y * 32;
    const float* src = (j0 < DD) ? Wq : (j0 < 2*DD ? Wk : Wv);
    int jb = j0 % DD;
    int tx = threadIdx.x, ty = threadIdx.y;
    #pragma unroll
    for (int i = 0; i < 32; i += 8)
        tile[ty + i][tx] = src[(long)(d0 + ty + i) * DD + jb + tx];
    __syncthreads();
    #pragma unroll
    for (int i = 0; i < 32; i += 8)
        out[(long)(j0 + ty + i) * DD + d0 + tx] = __float2half_rn(tile[tx][ty + i]);
}

__global__ void rms_jvp_kernel(const float* __restrict__ x, const float* __restrict__ dx,
                               const float* __restrict__ g,
                               __half* __restrict__ h, __half* __restrict__ dh) {
    __shared__ float sm[256];
    int row = blockIdx.x, tid = threadIdx.x;
    const float* xr  = x  + (long)row * DD;
    const float* dxr = dx + (long)row * DD;
    __half* hr  = h  + (long)row * DD;
    __half* dhr = dh + (long)row * DD;
    float s2 = 0.f, sxd = 0.f;
    for (int i = tid; i < DD; i += 256) { float xv = xr[i], dv = dxr[i]; s2 += xv*xv; sxd += xv*dv; }
    s2  = blk_sum(s2,  sm);
    sxd = blk_sum(sxd, sm);
    float r = rsqrtf(s2 / (float)DD + EPSV);
    float c = (sxd / (float)DD) * r * r * r;
    for (int i = tid; i < DD; i += 256) {
        float xv = xr[i], dv = dxr[i], gv = g[i];
        hr[i]  = __float2half_rn(xv * gv * r);
        dhr[i] = __float2half_rn(gv * (dv * r - xv * c));
    }
}

__global__ void rms_final_kernel(const float* __restrict__ x, const float* __restrict__ dx,
                                 const float* __restrict__ g, __half* __restrict__ out) {
    __shared__ float sm[256];
    int row = blockIdx.x, tid = threadIdx.x;
    const float* xr  = x  + (long)row * DD;
    const float* dxr = dx + (long)row * DD;
    __half* orow = out + (long)row * DD;
    float s2 = 0.f, sxd = 0.f;
    for (int i = tid; i < DD; i += 256) { float xv = xr[i], dv = dxr[i]; s2 += xv*xv; sxd += xv*dv; }
    s2  = blk_sum(s2,  sm);
    sxd = blk_sum(sxd, sm);
    float r = rsqrtf(s2 / (float)DD + EPSV);
    float c = (sxd / (float)DD) * r * r * r;
    for (int i = tid; i < DD; i += 256) {
        float xv = xr[i], dv = dxr[i], gv = g[i];
        orow[i] = __float2half_rn(xv * gv * r + gv * (dv * r - xv * c));
    }
}

__global__ void gelu_jvp_kernel(__half* __restrict__ u, __half* __restrict__ du) {
    long i = (long)blockIdx.x * blockDim.x + threadIdx.x;
    float x = __half2float(u[i]), d = __half2float(du[i]);
    const float c0 = 0.7978845608028654f, c1 = 0.044715f;
    float x2 = x * x;
    float t  = fast_tanh(c0 * (x + c1 * x * x2));
    float gl = 0.5f * x * (1.f + t);
    float dg = 0.5f * (1.f + t) + 0.5f * x * (1.f - t*t) * c0 * (1.f + 3.f * c1 * x2);
    u[i]  = __float2half_rn(gl);
    du[i] = __float2half_rn(dg * d);
}

// ===== fused attention JVP (unchanged, verified) =====
#define AT_LD 68
#define AT_LDV 72
#define AT_T68 (64*AT_LD)
#define AT_T72 (64*AT_LDV)
#define SQ    0
#define SDQ   (SQ + AT_T68)
#define SK    (SDQ + AT_T68)
#define SDK   (SK + 2*AT_T68)
#define SV    (SDK + 2*AT_T68)
#define SDV   (SV + 2*AT_T72)
#define SP    (SDV + 2*AT_T72)
#define SPDS  (SP + AT_T68)
#define SLRED (SPDS + AT_T68)
#define STRED (SLRED + 256)
#define SLRUN (STRED + 256)
#define STRUN (SLRUN + 64)
#define AT_FLOATS (STRUN + 64)

__global__ __launch_bounds__(256)
void attn_jvp_kernel(const float* __restrict__ qkv, __half* __restrict__ o2p,
                     __half* __restrict__ o2t, int has_dk)
{
    extern __shared__ float smem[];
    int mb = 15 - blockIdx.x;
    int bh = blockIdx.y;
    int b = bh >> 4, hh = bh & 15;
    int m0 = mb * 64;
    int nc = mb + 1;
    const long RW = 3 * DD;
    const long PRJ = (long)MM * 3 * DD;
    const float* qp = qkv + (long)(b*SS + m0) * RW + hh * HDD;
    int tid = threadIdx.x;
    int lane = tid & 31, wid = tid >> 5;
    int wm = wid >> 2, wn = wid & 3;
    int r = lane >> 2, cq = lane & 3;

    if (tid < 64) { smem[SLRUN + tid] = 0.f; smem[STRUN + tid] = 0.f; }

    {
        const float* kp = qkv + (long)(b*SS) * RW + DD + hh * HDD;
        const float* vp = qkv + (long)(b*SS) * RW + 2*DD + hh * HDD;
        #pragma unroll
        for (int i = 0; i < 4; i++) {
            int idx = tid + i * 256; int row = idx >> 4; int c4 = idx & 15;
            cpa16(&smem[SQ  + row*AT_LD  + c4*4], qp + (long)row * RW + c4*4);
            cpa16(&smem[SDQ + row*AT_LD  + c4*4], qp + PRJ + (long)row * RW + c4*4);
            cpa16(&smem[SK  + row*AT_LD  + c4*4], kp + (long)row * RW + c4*4);
            cpa16(&smem[SV  + row*AT_LDV + c4*4], vp + (long)row * RW + c4*4);
            cpa16(&smem[SDV + row*AT_LDV + c4*4], vp + PRJ + (long)row * RW + c4*4);
            if (has_dk)
                cpa16(&smem[SDK + row*AT_LD + c4*4], kp + PRJ + (long)row * RW + c4*4);
        }
        cpa_commit();
    }

    float o1[2][2][4] = {}, o2a[2][2][4] = {}, o3[2][2][4] = {};

    for (int ic = 0; ic < nc; ic++) {
        cpa_wait0();
        __syncthreads();
        int cur = ic & 1;
        if (ic + 1 < nc) {
            int nxt = (ic + 1) & 1;
            int kb = (ic + 1) * 64;
            const float* kp = qkv + (long)(b*SS + kb) * RW + DD + hh * HDD;
            const float* vp = qkv + (long)(b*SS + kb) * RW + 2*DD + hh * HDD;
            #pragma unroll
            for (int i = 0; i < 4; i++) {
                int idx = tid + i * 256; int row = idx >> 4; int c4 = idx & 15;
                cpa16(&smem[SK  + nxt*AT_T68 + row*AT_LD  + c4*4], kp + (long)row * RW + c4*4);
                cpa16(&smem[SV  + nxt*AT_T72 + row*AT_LDV + c4*4], vp + (long)row * RW + c4*4);
                cpa16(&smem[SDV + nxt*AT_T72 + row*AT_LDV + c4*4], vp + PRJ + (long)row * RW + c4*4);
                if (has_dk)
                    cpa16(&smem[SDK + nxt*AT_T68 + row*AT_LD + c4*4], kp + PRJ + (long)row * RW + c4*4);
            }
            cpa_commit();
        }
        const float* Ks  = smem + SK  + cur * AT_T68;
        const float* dKs = smem + SDK + cur * AT_T68;
        const float* Vs  = smem + SV  + cur * AT_T72;
        const float* dVs = smem + SDV + cur * AT_T72;

        float sacc[2][2][4] = {}, dsacc[2][2][4] = {};
        #pragma unroll
        for (int ks = 0; ks < 64; ks += 8) {
            uint32_t aq[2][4], adq[2][4], bk[2][2], bdk[2][2];
            #pragma unroll
            for (int mt = 0; mt < 2; mt++) {
                int base = (wm*32 + mt*16 + r) * AT_LD + ks + cq;
                aq[mt][0]  = __float_as_uint(smem[SQ  + base]);
                aq[mt][1]  = __float_as_uint(smem[SQ  + base + 8*AT_LD]);
                aq[mt][2]  = __float_as_uint(smem[SQ  + base + 4]);
                aq[mt][3]  = __float_as_uint(smem[SQ  + base + 8*AT_LD + 4]);
                adq[mt][0] = __float_as_uint(smem[SDQ + base]);
                adq[mt][1] = __float_as_uint(smem[SDQ + base + 8*AT_LD]);
                adq[mt][2] = __float_as_uint(smem[SDQ + base + 4]);
                adq[mt][3] = __float_as_uint(smem[SDQ + base + 8*AT_LD + 4]);
            }
            #pragma unroll
            for (int nt = 0; nt < 2; nt++) {
                int boff = (wn*16 + nt*8 + r) * AT_LD + ks + cq;
                bk[nt][0] = __float_as_uint(Ks[boff]);
                bk[nt][1] = __float_as_uint(Ks[boff + 4]);
                if (has_dk) {
                    bdk[nt][0] = __float_as_uint(dKs[boff]);
                    bdk[nt][1] = __float_as_uint(dKs[boff + 4]);
                }
            }
            #pragma unroll
            for (int mt = 0; mt < 2; mt++)
                #pragma unroll
                for (int nt = 0; nt < 2; nt++) {
                    mma8(sacc[mt][nt], aq[mt], bk[nt]);
                    mma8(dsacc[mt][nt], adq[mt], bk[nt]);
                    if (has_dk) mma8(dsacc[mt][nt], aq[mt], bdk[nt]);
                }
        }

        int diag = (ic == mb);
        float lp[2][2] = {}, tp[2][2] = {};
        #pragma unroll
        for (int mt = 0; mt < 2; mt++)
            #pragma unroll
            for (int nt = 0; nt < 2; nt++)
                #pragma unroll
                for (int j = 0; j < 4; j++) {
                    int row = wm*32 + mt*16 + r + (j >> 1) * 8;
                    int col = wn*16 + nt*8 + cq*2 + (j & 1);
                    float s  = sacc[mt][nt][j]  * 0.125f;
                    float ds = dsacc[mt][nt][j] * 0.125f;
                    float pv = (diag && col > row) ? 0.f : cvtf(__expf(s));
                    float pd = cvtf(pv * ds);
                    smem[SP   + row*AT_LD + col] = pv;
                    smem[SPDS + row*AT_LD + col] = pd;
                    lp[mt][j>>1] += pv;
                    tp[mt][j>>1] += pd;
                }
        #pragma unroll
        for (int mt = 0; mt < 2; mt++)
            #pragma unroll
            for (int hf = 0; hf < 2; hf++) {
                float lv = lp[mt][hf], tv = tp[mt][hf];
                lv += __shfl_xor_sync(0xffffffff, lv, 1);
                lv += __shfl_xor_sync(0xffffffff, lv, 2);
                tv += __shfl_xor_sync(0xffffffff, tv, 1);
                tv += __shfl_xor_sync(0xffffffff, tv, 2);
                if (cq == 0) {
                    int row = wm*32 + mt*16 + r + hf*8;
                    smem[SLRED + row*4 + wn] = lv;
                    smem[STRED + row*4 + wn] = tv;
                }
            }
        __syncthreads();
        if (tid < 64) {
            smem[SLRUN + tid] += smem[SLRED + tid*4] + smem[SLRED + tid*4+1]
                               + smem[SLRED + tid*4+2] + smem[SLRED + tid*4+3];
            smem[STRUN + tid] += smem[STRED + tid*4] + smem[STRED + tid*4+1]
                               + smem[STRED + tid*4+2] + smem[STRED + tid*4+3];
        }

        #pragma unroll
        for (int ks = 0; ks < 64; ks += 8) {
            uint32_t ap[2][4], apd[2][4], bv[2][2], bdv[2][2];
            #pragma unroll
            for (int mt = 0; mt < 2; mt++) {
                int base = (wm*32 + mt*16 + r) * AT_LD + ks + cq;
                ap[mt][0]  = __float_as_uint(smem[SP   + base]);
                ap[mt][1]  = __float_as_uint(smem[SP   + base + 8*AT_LD]);
                ap[mt][2]  = __float_as_uint(smem[SP   + base + 4]);
                ap[mt][3]  = __float_as_uint(smem[SP   + base + 8*AT_LD + 4]);
                apd[mt][0] = __float_as_uint(smem[SPDS + base]);
                apd[mt][1] = __float_as_uint(smem[SPDS + base + 8*AT_LD]);
                apd[mt][2] = __float_as_uint(smem[SPDS + base + 4]);
                apd[mt][3] = __float_as_uint(smem[SPDS + base + 8*AT_LD + 4]);
            }
            #pragma unroll
            for (int nt = 0; nt < 2; nt++) {
                int nb = wn*16 + nt*8;
                bv[nt][0]  = __float_as_uint(Vs[(ks + cq) * AT_LDV + nb + r]);
                bv[nt][1]  = __float_as_uint(Vs[(ks + cq + 4) * AT_LDV + nb + r]);
                bdv[nt][0] = __float_as_uint(dVs[(ks + cq) * AT_LDV + nb + r]);
                bdv[nt][1] = __float_as_uint(dVs[(ks + cq + 4) * AT_LDV + nb + r]);
            }
            #pragma unroll
            for (int mt = 0; mt < 2; mt++)
                #pragma unroll
                for (int nt = 0; nt < 2; nt++) {
                    mma8(o1[mt][nt],  ap[mt],  bv[nt]);
                    mma8(o2a[mt][nt], apd[mt], bv[nt]);
                    mma8(o3[mt][nt],  ap[mt],  bdv[nt]);
                }
        }
    }

    __syncthreads();
    #pragma unroll
    for (int mt = 0; mt < 2; mt++)
        #pragma unroll
        for (int nt = 0; nt < 2; nt++)
            #pragma unroll
            for (int hf = 0; hf < 2; hf++) {
                int lrow = wm*32 + mt*16 + r + hf*8;
                float inv = 1.f / smem[SLRUN + lrow];
                float tf = smem[STRUN + lrow] * inv;
                int j0 = hf * 2;
                float oa = o1[mt][nt][j0]   * inv;
                float ob = o1[mt][nt][j0+1] * inv;
                float da = (o2a[mt][nt][j0]   - tf * o1[mt][nt][j0])   * inv + o3[mt][nt][j0]   * inv;
                float db = (o2a[mt][nt][j0+1] - tf * o1[mt][nt][j0+1]) * inv + o3[mt][nt][j0+1] * inv;
                long idx = (long)(b*SS + m0 + lrow) * DD + hh * HDD + wn*16 + nt*8 + cq*2;
                *(half2*)(o2p + idx) = __floats2half2_rn(oa, ob);
                *(half2*)(o2t + idx) = __floats2half2_rn(da, db);
            }
}

// ===== FP16 GEMM: 128x128x64 CTA tile, 4 warps (2x2) of 64x64, 128 threads =====
// A: half [M][K], B: half [N][K] (pre-transposed). 3-stage cp.async, 2 CTA/SM.
template<bool CHALF, bool CVTO>
__global__ __launch_bounds__(128, 2)
void hgemm_kernel(const __half* __restrict__ A, const __half* __restrict__ B,
                  void* __restrict__ Cv, int M, int N, int K,
                  int lda, int ldb, int ldc, float beta)
{
    extern __shared__ __half hsm[];
    constexpr int LD = 72;                 // halfs per row (64 + 8 pad)
    constexpr int ASZ = 128 * LD;
    constexpr int STG = 2 * ASZ;
    int m0 = blockIdx.y * 128, n0 = blockIdx.x * 128;
    int nIt = K >> 6;
    int tid = threadIdx.x;
    int lane = tid & 31, wid = tid >> 5;
    int wm = wid & 1, wn = wid >> 1;       // 2 x 2 warps, 64x64 each
    int r = lane >> 2, cq = lane & 3;
    int c8 = tid & 7, mr = tid >> 3;       // loader: 16 rows/pass

    auto LOAD = [&](int kt, int st) {
        __half* As = hsm + st * STG;
        __half* Bs = As + ASZ;
        int k0 = kt * 64;
        #pragma unroll
        for (int i = 0; i < 8; i++) {
            int m = mr + i * 16;
            cpa16(&As[m * LD + c8 * 8], A + (long)(m0 + m) * lda + k0 + c8 * 8);
            cpa16(&Bs[m * LD + c8 * 8], B + (long)(n0 + m) * ldb + k0 + c8 * 8);
        }
    };

    float acc[4][8][4] = {};

    LOAD(0, 0); cpa_commit();
    if (nIt > 1) LOAD(1, 1);
    cpa_commit();

    for (int it = 0; it < nIt; ++it) {
        if (it < nIt - 1) asm volatile("cp.async.wait_group 1;" ::: "memory");
        else              asm volatile("cp.async.wait_group 0;" ::: "memory");
        __syncthreads();
        const __half* As = hsm + (it % 3) * STG;
        const __half* Bs = As + ASZ;
        #pragma unroll
        for (int ks = 0; ks < 64; ks += 16) {
            uint32_t af[4][4], bf[8][2];
            #pragma unroll
            for (int mt = 0; mt < 4; mt++) {
                int base = (wm * 64 + mt * 16 + r) * LD + ks + 2 * cq;
                af[mt][0] = *(const uint32_t*)&As[base];
                af[mt][1] = *(const uint32_t*)&As[base + 8 * LD];
                af[mt][2] = *(const uint32_t*)&As[base + 8];
                af[mt][3] = *(const uint32_t*)&As[base + 8 * LD + 8];
            }
            #pragma unroll
            for (int nt = 0; nt < 8; nt++) {
                int bb = (wn * 64 + nt * 8 + r) * LD + ks + 2 * cq;
                bf[nt][0] = *(const uint32_t*)&Bs[bb];
                bf[nt][1] = *(const uint32_t*)&Bs[bb + 8];
            }
            #pragma unroll
            for (int mt = 0; mt < 4; mt++)
                #pragma unroll
                for (int nt = 0; nt < 8; nt++)
                    mma16h(acc[mt][nt], af[mt], bf[nt]);
        }
        if (it + 2 < nIt) { LOAD(it + 2, (it + 2) % 3); cpa_commit(); }
    }

    #pragma unroll
    for (int mt = 0; mt < 4; mt++)
        #pragma unroll
        for (int nt = 0; nt < 8; nt++) {
            int gm = m0 + wm * 64 + mt * 16 + r;
            int gn = n0 + wn * 64 + nt * 8 + cq * 2;
            #pragma unroll
            for (int hf = 0; hf < 2; hf++) {
                long idx = (long)(gm + hf * 8) * ldc + gn;
                float v0 = acc[mt][nt][hf * 2];
                float v1 = acc[mt][nt][hf * 2 + 1];
                if (CHALF) {
                    *(half2*)((__half*)Cv + idx) = __floats2half2_rn(v0, v1);
                } else {
                    float* C = (float*)Cv;
                    if (beta != 0.f) { float2 o = *(float2*)(C + idx); v0 += o.x; v1 += o.y; }
                    if (CVTO) { v0 = cvtf(v0); v1 = cvtf(v1); }
                    *(float2*)(C + idx) = make_float2(v0, v1);
                }
            }
        }
}

// ===== SIMT GEMM (LoRA shapes), A may be half =====
#define BMs 64
#define BNs 64
#define BKs 16
template<bool TB, typename AT>
__global__ void gemm_kernel(const AT* __restrict__ A, const float* __restrict__ B,
                            float* __restrict__ C, int M, int N, int K,
                            int lda, int ldb, int ldc, float alpha, float beta, int docvt) {
    __shared__ float As[BKs][BMs + 1];
    __shared__ float Bs[BKs][BNs + 1];
    int tid = threadIdx.x;
    int tx = tid % 16, ty = tid / 16;
    int m0 = blockIdx.y * BMs, n0 = blockIdx.x * BNs;
    float acc[4][4] = {};
    for (int k0 = 0; k0 < K; k0 += BKs) {
        {
            int kk = tid % 16, mrel = tid / 16;
            #pragma unroll
            for (int i = 0; i < 4; i++) {
                int m = mrel + i * 16, gm = m0 + m;
                As[kk][m] = (gm < M) ? (float)A[(long)gm * lda + k0 + kk] : 0.f;
            }
        }
        if (!TB) {
            int n = tid % 64, kk0 = tid / 64;
            #pragma unroll
            for (int i = 0; i < 4; i++) {
                int kk = kk0 + i * 4, gn = n0 + n;
                Bs[kk][n] = (gn < N) ? B[(long)(k0 + kk) * ldb + gn] : 0.f;
            }
        } else {
            int kk = tid % 16, nrel = tid / 16;
            #pragma unroll
            for (int i = 0; i < 4; i++) {
                int n = nrel + i * 16, gn = n0 + n;
                Bs[kk][n] = (gn < N) ? B[(long)gn * ldb + k0 + kk] : 0.f;
            }
        }
        __syncthreads();
        #pragma unroll
        for (int kk = 0; kk < BKs; kk++) {
            float ra[4], rb[4];
            #pragma unroll
            for (int i = 0; i < 4; i++) ra[i] = As[kk][ty + 16 * i];
            #pragma unroll
            for (int j = 0; j < 4; j++) rb[j] = Bs[kk][tx + 16 * j];
            #pragma unroll
            for (int i = 0; i < 4; i++)
                #pragma unroll
                for (int j = 0; j < 4; j++)
                    acc[i][j] += ra[i] * rb[j];
        }
        __syncthreads();
    }
    #pragma unroll
    for (int i = 0; i < 4; i++) {
        int gm = m0 + ty + 16 * i;
        if (gm >= M) continue;
        #pragma unroll
        for (int j = 0; j < 4; j++) {
            int gn = n0 + tx + 16 * j;
            if (gn >= N) continue;
            long idx = (long)gm * ldc + gn;
            float prev = (beta != 0.f) ? beta * C[idx] : 0.f;
            float v = alpha * acc[i][j] + prev;
            C[idx] = docvt ? cvtf(v) : v;
        }
    }
}

template<bool CHALF, bool CVTO>
static void hg_launch(const __half* A, const __half* B, void* C, int M, int N, int K,
                      int lda, int ldb, int ldc, float beta) {
    dim3 grid(N / 128, M / 128);
    int smem = 3 * 2 * 128 * 72 * (int)sizeof(__half);
    cudaFuncSetAttribute(hgemm_kernel<CHALF, CVTO>, cudaFuncAttributeMaxDynamicSharedMemorySize, smem);
    hgemm_kernel<CHALF, CVTO><<<grid, 128, smem>>>(A, B, C, M, N, K, lda, ldb, ldc, beta);
}

extern "C" void kernel_launch(void* const* d_in, const int* in_sizes, int n_in,
                              void* d_out, int out_size) {
    const int*   ids = (const int*)  d_in[0];
    const float* emb = (const float*)d_in[1];
    const float* Wq  = (const float*)d_in[2];
    const float* Wk  = (const float*)d_in[3];
    const float* Wv  = (const float*)d_in[4];
    const float* Wo  = (const float*)d_in[5];
    const float* W1  = (const float*)d_in[6];
    const float* W2  = (const float*)d_in[7];
    const float* ln1 = (const float*)d_in[8];
    const float* ln2 = (const float*)d_in[9];
    const float* lnf = (const float*)d_in[10];
    const float* lmh = (const float*)d_in[11];
    const float* Aq0 = (const float*)d_in[12];
    const float* Av0 = (const float*)d_in[14];
    const float* Bq  = (const float*)d_in[17];
    const float* Bv  = (const float*)d_in[19];
    float* out = (float*)d_out;

    float *x2, *qkv2, *t;
    __half *h2, *o2, *u2, *wcat, *woc, *w1c, *w2c, *lmc;
    cudaGetSymbolAddress((void**)&x2,   g_x2);
    cudaGetSymbolAddress((void**)&h2,   g_h2);
    cudaGetSymbolAddress((void**)&qkv2, g_qkv2);
    cudaGetSymbolAddress((void**)&o2,   g_o2);
    cudaGetSymbolAddress((void**)&u2,   g_u2);
    cudaGetSymbolAddress((void**)&t,    g_t);
    cudaGetSymbolAddress((void**)&wcat, g_wcat);
    cudaGetSymbolAddress((void**)&woc,  g_woc);
    cudaGetSymbolAddress((void**)&w1c,  g_w1c);
    cudaGetSymbolAddress((void**)&w2c,  g_w2c);
    cudaGetSymbolAddress((void**)&lmc,  g_lmc);

    float*  x  = x2;  float*  dx = x2 + (long)MM*DD;
    __half* h  = h2;  __half* dh = h2 + (long)MM*DD;
    const long PRJ = (long)MM * 3*DD;
    int at_smem = AT_FLOATS * 4;
    cudaFuncSetAttribute(attn_jvp_kernel, cudaFuncAttributeMaxDynamicSharedMemorySize, at_smem);

    embed_kernel<<<(MM * DD) / 256, 256>>>(ids, emb, x, dx);
    transT_kernel<<<dim3(VV/32, DD/32), dim3(32,8)>>>(lmh, lmc, DD, VV);

    for (int l = 0; l < LL; l++) {
        const float* Aq0l = Aq0 + (long)l * RR * DD;
        const float* Av0l = Av0 + (long)l * RR * DD;
        const float* Bql  = Bq  + (long)l * DD * RR;
        const float* Bvl  = Bv  + (long)l * DD * RR;
        float lbeta = (l == 0) ? 0.f : 1.f;

        catwT_kernel<<<dim3(3*DD/32, DD/32), dim3(32,8)>>>(Wq + (long)l*DD*DD,
                                                           Wk + (long)l*DD*DD,
                                                           Wv + (long)l*DD*DD, wcat);
        transT_kernel<<<dim3(DD/32,  DD/32),  dim3(32,8)>>>(Wo + (long)l*DD*DD,  woc, DD,  DD);
        transT_kernel<<<dim3(FFD/32, DD/32),  dim3(32,8)>>>(W1 + (long)l*DD*FFD, w1c, DD,  FFD);
        transT_kernel<<<dim3(DD/32,  FFD/32), dim3(32,8)>>>(W2 + (long)l*FFD*DD, w2c, FFD, DD);

        rms_jvp_kernel<<<MM, 256>>>(x, dx, ln1 + (long)l * DD, h, dh);

        // qkv projection (fp16 TC). l=0 tangent is pure LoRA.
        if (l == 0)
            hg_launch<false, true>(h2, wcat, qkv2,   MM, 3*DD, DD, DD, DD, 3*DD, 0.f);
        else
            hg_launch<false, true>(h2, wcat, qkv2, 2*MM, 3*DD, DD, DD, DD, 3*DD, 0.f);

        // LoRA tangents (SIMT, tiny)
        gemm_kernel<true, __half><<<dim3(1, MM/BMs), 256>>>(h, Aq0l, t, MM, RR, DD, DD, DD, RR, 1.f, 0.f, 0);
        gemm_kernel<true, float ><<<dim3(DD/BNs, MM/BMs), 256>>>(t, Bql, qkv2 + PRJ,
            MM, DD, RR, RR, RR, 3*DD, LORA_SCALE, lbeta, 1);
        gemm_kernel<true, __half><<<dim3(1, MM/BMs), 256>>>(h, Av0l, t, MM, RR, DD, DD, DD, RR, 1.f, 0.f, 0);
        gemm_kernel<true, float ><<<dim3(DD/BNs, MM/BMs), 256>>>(t, Bvl, qkv2 + PRJ + 2*DD,
            MM, DD, RR, RR, RR, 3*DD, LORA_SCALE, lbeta, 1);

        attn_jvp_kernel<<<dim3(16, BB*HH), 256, at_smem>>>(qkv2, o2, o2 + (long)MM*DD, l > 0);

        // residual: x2 += o2 @ Wo^T-stored
        hg_launch<false, false>(o2, woc, x2, 2*MM, DD, DD, DD, DD, DD, 1.f);

        rms_jvp_kernel<<<MM, 256>>>(x, dx, ln2 + (long)l * DD, h, dh);
        hg_launch<true, false>(h2, w1c, u2, 2*MM, FFD, DD, DD, DD, FFD, 0.f);
        gelu_jvp_kernel<<<(MM * FFD) / 256, 256>>>(u2, u2 + (long)MM*FFD);
        hg_launch<false, false>(u2, w2c, x2, 2*MM, DD, FFD, FFD, FFD, DD, 1.f);
    }

    rms_final_kernel<<<MM, 256>>>(x, dx, lnf, h);
    hg_launch<false, false>(h, lmc, out, MM, VV, DD, DD, DD, VV, 0.f);
}

// round 16
// speedup vs baseline: 1.5527x; 1.0400x over previous
#include <cuda_runtime.h>
#include <cuda_fp16.h>
#include <math.h>
#include <stdint.h>

#define LL 2
#define BB 2
#define SS 1024
#define DD 1024
#define HH 16
#define HDD 64
#define FFD 4096
#define VV 32000
#define RR 16
#define MM (BB*SS)
#define LORA_SCALE 2.0f
#define EPSV 1e-6f

__device__ float  g_x2  [2L*MM*DD];
__device__ __half g_h2  [2L*MM*DD];
__device__ float  g_qkv2[2L*MM*3*DD];
__device__ __half g_o2  [2L*MM*DD];
__device__ __half g_u2  [2L*MM*FFD];
__device__ float  g_t   [MM*RR];
__device__ __half g_wcat[3*DD*DD];
__device__ __half g_woc [DD*DD];
__device__ __half g_w1c [FFD*DD];
__device__ __half g_w2c [DD*FFD];
__device__ __half g_lmc [VV*DD];

__device__ __forceinline__ float blk_sum(float v, float* sm) {
    int tid = threadIdx.x;
    sm[tid] = v; __syncthreads();
    for (int s = 128; s > 0; s >>= 1) { if (tid < s) sm[tid] += sm[tid + s]; __syncthreads(); }
    float r = sm[0]; __syncthreads(); return r;
}
__device__ __forceinline__ float cvtf(float x) {
    uint32_t u; asm("cvt.rna.tf32.f32 %0, %1;" : "=r"(u) : "f"(x));
    return __uint_as_float(u);
}
__device__ __forceinline__ void cpa16(void* dst, const void* src) {
    uint32_t d = (uint32_t)__cvta_generic_to_shared(dst);
    asm volatile("cp.async.cg.shared.global [%0], [%1], 16;" :: "r"(d), "l"(src));
}
__device__ __forceinline__ void cpa_commit() { asm volatile("cp.async.commit_group;" ::: "memory"); }
__device__ __forceinline__ void cpa_wait0()  { asm volatile("cp.async.wait_group 0;" ::: "memory"); }
__device__ __forceinline__ float fast_tanh(float x) {
    float e = __expf(2.f * x);
    return 1.f - 2.f / (e + 1.f);
}
__device__ __forceinline__ void mma8(float* c, const uint32_t* a, const uint32_t* b) {
    asm volatile(
        "mma.sync.aligned.m16n8k8.row.col.f32.tf32.tf32.f32 "
        "{%0,%1,%2,%3}, {%4,%5,%6,%7}, {%8,%9}, {%0,%1,%2,%3};"
        : "+f"(c[0]), "+f"(c[1]), "+f"(c[2]), "+f"(c[3])
        : "r"(a[0]), "r"(a[1]), "r"(a[2]), "r"(a[3]), "r"(b[0]), "r"(b[1]));
}
__device__ __forceinline__ void mma16h(float* c, const uint32_t* a, const uint32_t* b) {
    asm volatile(
        "mma.sync.aligned.m16n8k16.row.col.f32.f16.f16.f32 "
        "{%0,%1,%2,%3}, {%4,%5,%6,%7}, {%8,%9}, {%0,%1,%2,%3};"
        : "+f"(c[0]), "+f"(c[1]), "+f"(c[2]), "+f"(c[3])
        : "r"(a[0]), "r"(a[1]), "r"(a[2]), "r"(a[3]), "r"(b[0]), "r"(b[1]));
}
__device__ __forceinline__ void ldsm4(uint32_t& r0, uint32_t& r1, uint32_t& r2, uint32_t& r3,
                                      uint32_t addr) {
    asm volatile("ldmatrix.sync.aligned.m8n8.x4.shared.b16 {%0,%1,%2,%3}, [%4];"
                 : "=r"(r0), "=r"(r1), "=r"(r2), "=r"(r3) : "r"(addr));
}

__global__ void embed_kernel(const int* __restrict__ ids, const float* __restrict__ emb,
                             float* __restrict__ x, float* __restrict__ dx) {
    long i = (long)blockIdx.x * blockDim.x + threadIdx.x;
    int col = (int)(i % DD), row = (int)(i / DD);
    x[i]  = emb[(long)ids[row] * DD + col];
    dx[i] = 0.f;
}

__global__ void transT_kernel(const float* __restrict__ in, __half* __restrict__ out,
                              int K, int N) {
    __shared__ float tile[32][33];
    int n0 = blockIdx.x * 32, k0 = blockIdx.y * 32;
    int tx = threadIdx.x, ty = threadIdx.y;
    #pragma unroll
    for (int i = 0; i < 32; i += 8)
        tile[ty + i][tx] = in[(long)(k0 + ty + i) * N + n0 + tx];
    __syncthreads();
    #pragma unroll
    for (int i = 0; i < 32; i += 8)
        out[(long)(n0 + ty + i) * K + k0 + tx] = __float2half_rn(tile[tx][ty + i]);
}

__global__ void catwT_kernel(const float* __restrict__ Wq, const float* __restrict__ Wk,
                             const float* __restrict__ Wv, __half* __restrict__ out) {
    __shared__ float tile[32][33];
    int j0 = blockIdx.x * 32, d0 = blockIdx.y * 32;
    const float* src = (j0 < DD) ? Wq : (j0 < 2*DD ? Wk : Wv);
    int jb = j0 % DD;
    int tx = threadIdx.x, ty = threadIdx.y;
    #pragma unroll
    for (int i = 0; i < 32; i += 8)
        tile[ty + i][tx] = src[(long)(d0 + ty + i) * DD + jb + tx];
    __syncthreads();
    #pragma unroll
    for (int i = 0; i < 32; i += 8)
        out[(long)(j0 + ty + i) * DD + d0 + tx] = __float2half_rn(tile[tx][ty + i]);
}

__global__ void rms_jvp_kernel(const float* __restrict__ x, const float* __restrict__ dx,
                               const float* __restrict__ g,
                               __half* __restrict__ h, __half* __restrict__ dh) {
    __shared__ float sm[256];
    int row = blockIdx.x, tid = threadIdx.x;
    const float* xr  = x  + (long)row * DD;
    const float* dxr = dx + (long)row * DD;
    __half* hr  = h  + (long)row * DD;
    __half* dhr = dh + (long)row * DD;
    float s2 = 0.f, sxd = 0.f;
    for (int i = tid; i < DD; i += 256) { float xv = xr[i], dv = dxr[i]; s2 += xv*xv; sxd += xv*dv; }
    s2  = blk_sum(s2,  sm);
    sxd = blk_sum(sxd, sm);
    float r = rsqrtf(s2 / (float)DD + EPSV);
    float c = (sxd / (float)DD) * r * r * r;
    for (int i = tid; i < DD; i += 256) {
        float xv = xr[i], dv = dxr[i], gv = g[i];
        hr[i]  = __float2half_rn(xv * gv * r);
        dhr[i] = __float2half_rn(gv * (dv * r - xv * c));
    }
}

__global__ void rms_final_kernel(const float* __restrict__ x, const float* __restrict__ dx,
                                 const float* __restrict__ g, __half* __restrict__ out) {
    __shared__ float sm[256];
    int row = blockIdx.x, tid = threadIdx.x;
    const float* xr  = x  + (long)row * DD;
    const float* dxr = dx + (long)row * DD;
    __half* orow = out + (long)row * DD;
    float s2 = 0.f, sxd = 0.f;
    for (int i = tid; i < DD; i += 256) { float xv = xr[i], dv = dxr[i]; s2 += xv*xv; sxd += xv*dv; }
    s2  = blk_sum(s2,  sm);
    sxd = blk_sum(sxd, sm);
    float r = rsqrtf(s2 / (float)DD + EPSV);
    float c = (sxd / (float)DD) * r * r * r;
    for (int i = tid; i < DD; i += 256) {
        float xv = xr[i], dv = dxr[i], gv = g[i];
        orow[i] = __float2half_rn(xv * gv * r + gv * (dv * r - xv * c));
    }
}

__global__ void gelu_jvp_kernel(__half* __restrict__ u, __half* __restrict__ du) {
    long i = (long)blockIdx.x * blockDim.x + threadIdx.x;
    float x = __half2float(u[i]), d = __half2float(du[i]);
    const float c0 = 0.7978845608028654f, c1 = 0.044715f;
    float x2 = x * x;
    float t  = fast_tanh(c0 * (x + c1 * x * x2));
    float gl = 0.5f * x * (1.f + t);
    float dg = 0.5f * (1.f + t) + 0.5f * x * (1.f - t*t) * c0 * (1.f + 3.f * c1 * x2);
    u[i]  = __float2half_rn(gl);
    du[i] = __float2half_rn(dg * d);
}

// ===== fused attention JVP (unchanged, verified) =====
#define AT_LD 68
#define AT_LDV 72
#define AT_T68 (64*AT_LD)
#define AT_T72 (64*AT_LDV)
#define SQ    0
#define SDQ   (SQ + AT_T68)
#define SK    (SDQ + AT_T68)
#define SDK   (SK + 2*AT_T68)
#define SV    (SDK + 2*AT_T68)
#define SDV   (SV + 2*AT_T72)
#define SP    (SDV + 2*AT_T72)
#define SPDS  (SP + AT_T68)
#define SLRED (SPDS + AT_T68)
#define STRED (SLRED + 256)
#define SLRUN (STRED + 256)
#define STRUN (SLRUN + 64)
#define AT_FLOATS (STRUN + 64)

__global__ __launch_bounds__(256)
void attn_jvp_kernel(const float* __restrict__ qkv, __half* __restrict__ o2p,
                     __half* __restrict__ o2t, int has_dk)
{
    extern __shared__ float smem[];
    int mb = 15 - blockIdx.x;
    int bh = blockIdx.y;
    int b = bh >> 4, hh = bh & 15;
    int m0 = mb * 64;
    int nc = mb + 1;
    const long RW = 3 * DD;
    const long PRJ = (long)MM * 3 * DD;
    const float* qp = qkv + (long)(b*SS + m0) * RW + hh * HDD;
    int tid = threadIdx.x;
    int lane = tid & 31, wid = tid >> 5;
    int wm = wid >> 2, wn = wid & 3;
    int r = lane >> 2, cq = lane & 3;

    if (tid < 64) { smem[SLRUN + tid] = 0.f; smem[STRUN + tid] = 0.f; }

    {
        const float* kp = qkv + (long)(b*SS) * RW + DD + hh * HDD;
        const float* vp = qkv + (long)(b*SS) * RW + 2*DD + hh * HDD;
        #pragma unroll
        for (int i = 0; i < 4; i++) {
            int idx = tid + i * 256; int row = idx >> 4; int c4 = idx & 15;
            cpa16(&smem[SQ  + row*AT_LD  + c4*4], qp + (long)row * RW + c4*4);
            cpa16(&smem[SDQ + row*AT_LD  + c4*4], qp + PRJ + (long)row * RW + c4*4);
            cpa16(&smem[SK  + row*AT_LD  + c4*4], kp + (long)row * RW + c4*4);
            cpa16(&smem[SV  + row*AT_LDV + c4*4], vp + (long)row * RW + c4*4);
            cpa16(&smem[SDV + row*AT_LDV + c4*4], vp + PRJ + (long)row * RW + c4*4);
            if (has_dk)
                cpa16(&smem[SDK + row*AT_LD + c4*4], kp + PRJ + (long)row * RW + c4*4);
        }
        cpa_commit();
    }

    float o1[2][2][4] = {}, o2a[2][2][4] = {}, o3[2][2][4] = {};

    for (int ic = 0; ic < nc; ic++) {
        cpa_wait0();
        __syncthreads();
        int cur = ic & 1;
        if (ic + 1 < nc) {
            int nxt = (ic + 1) & 1;
            int kb = (ic + 1) * 64;
            const float* kp = qkv + (long)(b*SS + kb) * RW + DD + hh * HDD;
            const float* vp = qkv + (long)(b*SS + kb) * RW + 2*DD + hh * HDD;
            #pragma unroll
            for (int i = 0; i < 4; i++) {
                int idx = tid + i * 256; int row = idx >> 4; int c4 = idx & 15;
                cpa16(&smem[SK  + nxt*AT_T68 + row*AT_LD  + c4*4], kp + (long)row * RW + c4*4);
                cpa16(&smem[SV  + nxt*AT_T72 + row*AT_LDV + c4*4], vp + (long)row * RW + c4*4);
                cpa16(&smem[SDV + nxt*AT_T72 + row*AT_LDV + c4*4], vp + PRJ + (long)row * RW + c4*4);
                if (has_dk)
                    cpa16(&smem[SDK + nxt*AT_T68 + row*AT_LD + c4*4], kp + PRJ + (long)row * RW + c4*4);
            }
            cpa_commit();
        }
        const float* Ks  = smem + SK  + cur * AT_T68;
        const float* dKs = smem + SDK + cur * AT_T68;
        const float* Vs  = smem + SV  + cur * AT_T72;
        const float* dVs = smem + SDV + cur * AT_T72;

        float sacc[2][2][4] = {}, dsacc[2][2][4] = {};
        #pragma unroll
        for (int ks = 0; ks < 64; ks += 8) {
            uint32_t aq[2][4], adq[2][4], bk[2][2], bdk[2][2];
            #pragma unroll
            for (int mt = 0; mt < 2; mt++) {
                int base = (wm*32 + mt*16 + r) * AT_LD + ks + cq;
                aq[mt][0]  = __float_as_uint(smem[SQ  + base]);
                aq[mt][1]  = __float_as_uint(smem[SQ  + base + 8*AT_LD]);
                aq[mt][2]  = __float_as_uint(smem[SQ  + base + 4]);
                aq[mt][3]  = __float_as_uint(smem[SQ  + base + 8*AT_LD + 4]);
                adq[mt][0] = __float_as_uint(smem[SDQ + base]);
                adq[mt][1] = __float_as_uint(smem[SDQ + base + 8*AT_LD]);
                adq[mt][2] = __float_as_uint(smem[SDQ + base + 4]);
                adq[mt][3] = __float_as_uint(smem[SDQ + base + 8*AT_LD + 4]);
            }
            #pragma unroll
            for (int nt = 0; nt < 2; nt++) {
                int boff = (wn*16 + nt*8 + r) * AT_LD + ks + cq;
                bk[nt][0] = __float_as_uint(Ks[boff]);
                bk[nt][1] = __float_as_uint(Ks[boff + 4]);
                if (has_dk) {
                    bdk[nt][0] = __float_as_uint(dKs[boff]);
                    bdk[nt][1] = __float_as_uint(dKs[boff + 4]);
                }
            }
            #pragma unroll
            for (int mt = 0; mt < 2; mt++)
                #pragma unroll
                for (int nt = 0; nt < 2; nt++) {
                    mma8(sacc[mt][nt], aq[mt], bk[nt]);
                    mma8(dsacc[mt][nt], adq[mt], bk[nt]);
                    if (has_dk) mma8(dsacc[mt][nt], aq[mt], bdk[nt]);
                }
        }

        int diag = (ic == mb);
        float lp[2][2] = {}, tp[2][2] = {};
        #pragma unroll
        for (int mt = 0; mt < 2; mt++)
            #pragma unroll
            for (int nt = 0; nt < 2; nt++)
                #pragma unroll
                for (int j = 0; j < 4; j++) {
                    int row = wm*32 + mt*16 + r + (j >> 1) * 8;
                    int col = wn*16 + nt*8 + cq*2 + (j & 1);
                    float s  = sacc[mt][nt][j]  * 0.125f;
                    float ds = dsacc[mt][nt][j] * 0.125f;
                    float pv = (diag && col > row) ? 0.f : cvtf(__expf(s));
                    float pd = cvtf(pv * ds);
                    smem[SP   + row*AT_LD + col] = pv;
                    smem[SPDS + row*AT_LD + col] = pd;
                    lp[mt][j>>1] += pv;
                    tp[mt][j>>1] += pd;
                }
        #pragma unroll
        for (int mt = 0; mt < 2; mt++)
            #pragma unroll
            for (int hf = 0; hf < 2; hf++) {
                float lv = lp[mt][hf], tv = tp[mt][hf];
                lv += __shfl_xor_sync(0xffffffff, lv, 1);
                lv += __shfl_xor_sync(0xffffffff, lv, 2);
                tv += __shfl_xor_sync(0xffffffff, tv, 1);
                tv += __shfl_xor_sync(0xffffffff, tv, 2);
                if (cq == 0) {
                    int row = wm*32 + mt*16 + r + hf*8;
                    smem[SLRED + row*4 + wn] = lv;
                    smem[STRED + row*4 + wn] = tv;
                }
            }
        __syncthreads();
        if (tid < 64) {
            smem[SLRUN + tid] += smem[SLRED + tid*4] + smem[SLRED + tid*4+1]
                               + smem[SLRED + tid*4+2] + smem[SLRED + tid*4+3];
            smem[STRUN + tid] += smem[STRED + tid*4] + smem[STRED + tid*4+1]
                               + smem[STRED + tid*4+2] + smem[STRED + tid*4+3];
        }

        #pragma unroll
        for (int ks = 0; ks < 64; ks += 8) {
            uint32_t ap[2][4], apd[2][4], bv[2][2], bdv[2][2];
            #pragma unroll
            for (int mt = 0; mt < 2; mt++) {
                int base = (wm*32 + mt*16 + r) * AT_LD + ks + cq;
                ap[mt][0]  = __float_as_uint(smem[SP   + base]);
                ap[mt][1]  = __float_as_uint(smem[SP   + base + 8*AT_LD]);
                ap[mt][2]  = __float_as_uint(smem[SP   + base + 4]);
                ap[mt][3]  = __float_as_uint(smem[SP   + base + 8*AT_LD + 4]);
                apd[mt][0] = __float_as_uint(smem[SPDS + base]);
                apd[mt][1] = __float_as_uint(smem[SPDS + base + 8*AT_LD]);
                apd[mt][2] = __float_as_uint(smem[SPDS + base + 4]);
                apd[mt][3] = __float_as_uint(smem[SPDS + base + 8*AT_LD + 4]);
            }
            #pragma unroll
            for (int nt = 0; nt < 2; nt++) {
                int nb = wn*16 + nt*8;
                bv[nt][0]  = __float_as_uint(Vs[(ks + cq) * AT_LDV + nb + r]);
                bv[nt][1]  = __float_as_uint(Vs[(ks + cq + 4) * AT_LDV + nb + r]);
                bdv[nt][0] = __float_as_uint(dVs[(ks + cq) * AT_LDV + nb + r]);
                bdv[nt][1] = __float_as_uint(dVs[(ks + cq + 4) * AT_LDV + nb + r]);
            }
            #pragma unroll
            for (int mt = 0; mt < 2; mt++)
                #pragma unroll
                for (int nt = 0; nt < 2; nt++) {
                    mma8(o1[mt][nt],  ap[mt],  bv[nt]);
                    mma8(o2a[mt][nt], apd[mt], bv[nt]);
                    mma8(o3[mt][nt],  ap[mt],  bdv[nt]);
                }
        }
    }

    __syncthreads();
    #pragma unroll
    for (int mt = 0; mt < 2; mt++)
        #pragma unroll
        for (int nt = 0; nt < 2; nt++)
            #pragma unroll
            for (int hf = 0; hf < 2; hf++) {
                int lrow = wm*32 + mt*16 + r + hf*8;
                float inv = 1.f / smem[SLRUN + lrow];
                float tf = smem[STRUN + lrow] * inv;
                int j0 = hf * 2;
                float oa = o1[mt][nt][j0]   * inv;
                float ob = o1[mt][nt][j0+1] * inv;
                float da = (o2a[mt][nt][j0]   - tf * o1[mt][nt][j0])   * inv + o3[mt][nt][j0]   * inv;
                float db = (o2a[mt][nt][j0+1] - tf * o1[mt][nt][j0+1]) * inv + o3[mt][nt][j0+1] * inv;
                long idx = (long)(b*SS + m0 + lrow) * DD + hh * HDD + wn*16 + nt*8 + cq*2;
                *(half2*)(o2p + idx) = __floats2half2_rn(oa, ob);
                *(half2*)(o2t + idx) = __floats2half2_rn(da, db);
            }
}

// ===== FP16 GEMM: 128x128x64 CTA, 4 warps (2x2) of 64x64, ldmatrix fragments =====
template<bool CHALF, bool CVTO>
__global__ __launch_bounds__(128, 2)
void hgemm_kernel(const __half* __restrict__ A, const __half* __restrict__ B,
                  void* __restrict__ Cv, int M, int N, int K,
                  int lda, int ldb, int ldc, float beta)
{
    extern __shared__ __half hsm[];
    constexpr int LD = 72;
    constexpr int ASZ = 128 * LD;
    constexpr int STG = 2 * ASZ;
    int m0 = blockIdx.y * 128, n0 = blockIdx.x * 128;
    int nIt = K >> 6;
    int tid = threadIdx.x;
    int lane = tid & 31, wid = tid >> 5;
    int wm = wid & 1, wn = wid >> 1;
    int r = lane >> 2, cq = lane & 3;
    int c8 = tid & 7, mr = tid >> 3;

    // ldmatrix lane-dependent element offsets (halfs)
    int laneAoff = (wm * 64 + ((lane >> 3) & 1) * 8 + (lane & 7)) * LD + (lane >> 4) * 8;
    int laneBoff = (wn * 64 + (lane >> 4) * 8 + (lane & 7)) * LD + ((lane >> 3) & 1) * 8;

    auto LOAD = [&](int kt, int st) {
        __half* As = hsm + st * STG;
        __half* Bs = As + ASZ;
        int k0 = kt * 64;
        #pragma unroll
        for (int i = 0; i < 8; i++) {
            int m = mr + i * 16;
            cpa16(&As[m * LD + c8 * 8], A + (long)(m0 + m) * lda + k0 + c8 * 8);
            cpa16(&Bs[m * LD + c8 * 8], B + (long)(n0 + m) * ldb + k0 + c8 * 8);
        }
    };

    float acc[4][8][4] = {};

    LOAD(0, 0); cpa_commit();
    if (nIt > 1) LOAD(1, 1);
    cpa_commit();

    for (int it = 0; it < nIt; ++it) {
        if (it < nIt - 1) asm volatile("cp.async.wait_group 1;" ::: "memory");
        else              asm volatile("cp.async.wait_group 0;" ::: "memory");
        __syncthreads();
        const __half* As = hsm + (it % 3) * STG;
        const __half* Bs = As + ASZ;
        uint32_t As32 = (uint32_t)__cvta_generic_to_shared(As);
        uint32_t Bs32 = (uint32_t)__cvta_generic_to_shared(Bs);
        #pragma unroll
        for (int ks = 0; ks < 64; ks += 16) {
            uint32_t af[4][4], bf[8][2];
            #pragma unroll
            for (int mt = 0; mt < 4; mt++)
                ldsm4(af[mt][0], af[mt][1], af[mt][2], af[mt][3],
                      As32 + 2u * (laneAoff + mt * 16 * LD + ks));
            #pragma unroll
            for (int p = 0; p < 4; p++)
                ldsm4(bf[2*p][0], bf[2*p][1], bf[2*p+1][0], bf[2*p+1][1],
                      Bs32 + 2u * (laneBoff + p * 16 * LD + ks));
            #pragma unroll
            for (int mt = 0; mt < 4; mt++)
                #pragma unroll
                for (int nt = 0; nt < 8; nt++)
                    mma16h(acc[mt][nt], af[mt], bf[nt]);
        }
        if (it + 2 < nIt) { LOAD(it + 2, (it + 2) % 3); cpa_commit(); }
    }

    #pragma unroll
    for (int mt = 0; mt < 4; mt++)
        #pragma unroll
        for (int nt = 0; nt < 8; nt++) {
            int gm = m0 + wm * 64 + mt * 16 + r;
            int gn = n0 + wn * 64 + nt * 8 + cq * 2;
            #pragma unroll
            for (int hf = 0; hf < 2; hf++) {
                long idx = (long)(gm + hf * 8) * ldc + gn;
                float v0 = acc[mt][nt][hf * 2];
                float v1 = acc[mt][nt][hf * 2 + 1];
                if (CHALF) {
                    *(half2*)((__half*)Cv + idx) = __floats2half2_rn(v0, v1);
                } else {
                    float* C = (float*)Cv;
                    if (beta != 0.f) { float2 o = *(float2*)(C + idx); v0 += o.x; v1 += o.y; }
                    if (CVTO) { v0 = cvtf(v0); v1 = cvtf(v1); }
                    *(float2*)(C + idx) = make_float2(v0, v1);
                }
            }
        }
}

// ===== SIMT GEMM (LoRA shapes), A may be half =====
#define BMs 64
#define BNs 64
#define BKs 16
template<bool TB, typename AT>
__global__ void gemm_kernel(const AT* __restrict__ A, const float* __restrict__ B,
                            float* __restrict__ C, int M, int N, int K,
                            int lda, int ldb, int ldc, float alpha, float beta, int docvt) {
    __shared__ float As[BKs][BMs + 1];
    __shared__ float Bs[BKs][BNs + 1];
    int tid = threadIdx.x;
    int tx = tid % 16, ty = tid / 16;
    int m0 = blockIdx.y * BMs, n0 = blockIdx.x * BNs;
    float acc[4][4] = {};
    for (int k0 = 0; k0 < K; k0 += BKs) {
        {
            int kk = tid % 16, mrel = tid / 16;
            #pragma unroll
            for (int i = 0; i < 4; i++) {
                int m = mrel + i * 16, gm = m0 + m;
                As[kk][m] = (gm < M) ? (float)A[(long)gm * lda + k0 + kk] : 0.f;
            }
        }
        if (!TB) {
            int n = tid % 64, kk0 = tid / 64;
            #pragma unroll
            for (int i = 0; i < 4; i++) {
                int kk = kk0 + i * 4, gn = n0 + n;
                Bs[kk][n] = (gn < N) ? B[(long)(k0 + kk) * ldb + gn] : 0.f;
            }
        } else {
            int kk = tid % 16, nrel = tid / 16;
            #pragma unroll
            for (int i = 0; i < 4; i++) {
                int n = nrel + i * 16, gn = n0 + n;
                Bs[kk][n] = (gn < N) ? B[(long)gn * ldb + k0 + kk] : 0.f;
            }
        }
        __syncthreads();
        #pragma unroll
        for (int kk = 0; kk < BKs; kk++) {
            float ra[4], rb[4];
            #pragma unroll
            for (int i = 0; i < 4; i++) ra[i] = As[kk][ty + 16 * i];
            #pragma unroll
            for (int j = 0; j < 4; j++) rb[j] = Bs[kk][tx + 16 * j];
            #pragma unroll
            for (int i = 0; i < 4; i++)
                #pragma unroll
                for (int j = 0; j < 4; j++)
                    acc[i][j] += ra[i] * rb[j];
        }
        __syncthreads();
    }
    #pragma unroll
    for (int i = 0; i < 4; i++) {
        int gm = m0 + ty + 16 * i;
        if (gm >= M) continue;
        #pragma unroll
        for (int j = 0; j < 4; j++) {
            int gn = n0 + tx + 16 * j;
            if (gn >= N) continue;
            long idx = (long)gm * ldc + gn;
            float prev = (beta != 0.f) ? beta * C[idx] : 0.f;
            float v = alpha * acc[i][j] + prev;
            C[idx] = docvt ? cvtf(v) : v;
        }
    }
}

template<bool CHALF, bool CVTO>
static void hg_launch(const __half* A, const __half* B, void* C, int M, int N, int K,
                      int lda, int ldb, int ldc, float beta) {
    dim3 grid(N / 128, M / 128);
    int smem = 3 * 2 * 128 * 72 * (int)sizeof(__half);
    cudaFuncSetAttribute(hgemm_kernel<CHALF, CVTO>, cudaFuncAttributeMaxDynamicSharedMemorySize, smem);
    hgemm_kernel<CHALF, CVTO><<<grid, 128, smem>>>(A, B, C, M, N, K, lda, ldb, ldc, beta);
}

extern "C" void kernel_launch(void* const* d_in, const int* in_sizes, int n_in,
                              void* d_out, int out_size) {
    const int*   ids = (const int*)  d_in[0];
    const float* emb = (const float*)d_in[1];
    const float* Wq  = (const float*)d_in[2];
    const float* Wk  = (const float*)d_in[3];
    const float* Wv  = (const float*)d_in[4];
    const float* Wo  = (const float*)d_in[5];
    const float* W1  = (const float*)d_in[6];
    const float* W2  = (const float*)d_in[7];
    const float* ln1 = (const float*)d_in[8];
    const float* ln2 = (const float*)d_in[9];
    const float* lnf = (const float*)d_in[10];
    const float* lmh = (const float*)d_in[11];
    const float* Aq0 = (const float*)d_in[12];
    const float* Av0 = (const float*)d_in[14];
    const float* Bq  = (const float*)d_in[17];
    const float* Bv  = (const float*)d_in[19];
    float* out = (float*)d_out;

    float *x2, *qkv2, *t;
    __half *h2, *o2, *u2, *wcat, *woc, *w1c, *w2c, *lmc;
    cudaGetSymbolAddress((void**)&x2,   g_x2);
    cudaGetSymbolAddress((void**)&h2,   g_h2);
    cudaGetSymbolAddress((void**)&qkv2, g_qkv2);
    cudaGetSymbolAddress((void**)&o2,   g_o2);
    cudaGetSymbolAddress((void**)&u2,   g_u2);
    cudaGetSymbolAddress((void**)&t,    g_t);
    cudaGetSymbolAddress((void**)&wcat, g_wcat);
    cudaGetSymbolAddress((void**)&woc,  g_woc);
    cudaGetSymbolAddress((void**)&w1c,  g_w1c);
    cudaGetSymbolAddress((void**)&w2c,  g_w2c);
    cudaGetSymbolAddress((void**)&lmc,  g_lmc);

    float*  x  = x2;  float*  dx = x2 + (long)MM*DD;
    __half* h  = h2;  __half* dh = h2 + (long)MM*DD;
    const long PRJ = (long)MM * 3*DD;
    int at_smem = AT_FLOATS * 4;
    cudaFuncSetAttribute(attn_jvp_kernel, cudaFuncAttributeMaxDynamicSharedMemorySize, at_smem);

    // Launch order chosen so ncu (-s 5 -c 1) captures the first qkv hgemm (launch #6).
    embed_kernel<<<(MM * DD) / 256, 256>>>(ids, emb, x, dx);                          // 1

    for (int l = 0; l < LL; l++) {
        const float* Aq0l = Aq0 + (long)l * RR * DD;
        const float* Av0l = Av0 + (long)l * RR * DD;
        const float* Bql  = Bq  + (long)l * DD * RR;
        const float* Bvl  = Bv  + (long)l * DD * RR;
        float lbeta = (l == 0) ? 0.f : 1.f;

        rms_jvp_kernel<<<MM, 256>>>(x, dx, ln1 + (long)l * DD, h, dh);                // 2
        catwT_kernel<<<dim3(3*DD/32, DD/32), dim3(32,8)>>>(Wq + (long)l*DD*DD,        // 3
                                                           Wk + (long)l*DD*DD,
                                                           Wv + (long)l*DD*DD, wcat);
        transT_kernel<<<dim3(DD/32,  DD/32),  dim3(32,8)>>>(Wo + (long)l*DD*DD,  woc, DD,  DD);   // 4
        transT_kernel<<<dim3(FFD/32, DD/32),  dim3(32,8)>>>(W1 + (long)l*DD*FFD, w1c, DD,  FFD);  // 5

        // qkv projection (fp16 TC, ldmatrix). l=0 tangent is pure LoRA.              // 6 <- ncu capture
        if (l == 0)
            hg_launch<false, true>(h2, wcat, qkv2,   MM, 3*DD, DD, DD, DD, 3*DD, 0.f);
        else
            hg_launch<false, true>(h2, wcat, qkv2, 2*MM, 3*DD, DD, DD, DD, 3*DD, 0.f);

        transT_kernel<<<dim3(DD/32,  FFD/32), dim3(32,8)>>>(W2 + (long)l*FFD*DD, w2c, FFD, DD);

        // LoRA tangents (SIMT, tiny)
        gemm_kernel<true, __half><<<dim3(1, MM/BMs), 256>>>(h, Aq0l, t, MM, RR, DD, DD, DD, RR, 1.f, 0.f, 0);
        gemm_kernel<true, float ><<<dim3(DD/BNs, MM/BMs), 256>>>(t, Bql, qkv2 + PRJ,
            MM, DD, RR, RR, RR, 3*DD, LORA_SCALE, lbeta, 1);
        gemm_kernel<true, __half><<<dim3(1, MM/BMs), 256>>>(h, Av0l, t, MM, RR, DD, DD, DD, RR, 1.f, 0.f, 0);
        gemm_kernel<true, float ><<<dim3(DD/BNs, MM/BMs), 256>>>(t, Bvl, qkv2 + PRJ + 2*DD,
            MM, DD, RR, RR, RR, 3*DD, LORA_SCALE, lbeta, 1);

        attn_jvp_kernel<<<dim3(16, BB*HH), 256, at_smem>>>(qkv2, o2, o2 + (long)MM*DD, l > 0);

        // residual: x2 += o2 @ Wo^T-stored
        hg_launch<false, false>(o2, woc, x2, 2*MM, DD, DD, DD, DD, DD, 1.f);

        rms_jvp_kernel<<<MM, 256>>>(x, dx, ln2 + (long)l * DD, h, dh);
        hg_launch<true, false>(h2, w1c, u2, 2*MM, FFD, DD, DD, DD, FFD, 0.f);
        gelu_jvp_kernel<<<(MM * FFD) / 256, 256>>>(u2, u2 + (long)MM*FFD);
        hg_launch<false, false>(u2, w2c, x2, 2*MM, DD, FFD, FFD, FFD, DD, 1.f);
    }

    rms_final_kernel<<<MM, 256>>>(x, dx, lnf, h);
    transT_kernel<<<dim3(VV/32, DD/32), dim3(32,8)>>>(lmh, lmc, DD, VV);
    hg_launch<false, false>(h, lmc, out, MM, VV, DD, DD, DD, VV, 0.f);
}